// round 14
// baseline (speedup 1.0000x reference)
#include <cuda_runtime.h>
#include <cuda_bf16.h>
#include <cstdint>
#include <math.h>

// AttentionWithPairBias: B=1, L=768, C_S=384, C_Z=128, H=8, HD=48
#define L 768
#define CS 384
#define NH 8
#define HD 48
#define LL (L*L)
#define OPS (L*CS)
#define NSPLIT 4

// -------------------- scratch (device globals; no allocs) --------------------
__device__ float g_bias[(size_t)NH*LL];  // pair bias (fp32), read by attn
__device__ float g_gate[L*CS];
__device__ float g_opart[NSPLIT*OPS];    // unnormalized O per j-split
__device__ float2 g_stat[NSPLIT*NH*L];   // per split: (m, l) per (h, i)
__device__ __nv_bfloat16 g_ah[L*CS], g_al[L*CS];         // layernorm(single) hi/lo
__device__ __nv_bfloat16 g_wh[4*CS*CS], g_wl[4*CS*CS];   // Wq|Wk|Wv|Wg rows, hi/lo
__device__ __nv_bfloat16 g_qh[L*CS], g_ql[L*CS];         // Q hi/lo
__device__ __nv_bfloat16 g_kh[L*CS], g_kl[L*CS];         // K hi/lo
__device__ __nv_bfloat16 g_vth[CS*L], g_vtl[CS*L];       // V^T hi/lo: [d][j]

// -------------------- warp helpers --------------------
__device__ __forceinline__ float warp_sum(float v){
#pragma unroll
    for (int o = 16; o; o >>= 1) v += __shfl_xor_sync(0xffffffffu, v, o);
    return v;
}

// -------------------- mma.sync / ldmatrix / cp.async (plain PTX, sm_80+) ----
__device__ __forceinline__ uint32_t smem_u32(const void* p){
    uint32_t a;
    asm("{ .reg .u64 t; cvta.to.shared.u64 t, %1; cvt.u32.u64 %0, t; }" : "=r"(a) : "l"(p));
    return a;
}
__device__ __forceinline__ void ldsm4(uint32_t* r, uint32_t addr){
    asm volatile("ldmatrix.sync.aligned.m8n8.x4.shared.b16 {%0,%1,%2,%3}, [%4];"
        : "=r"(r[0]), "=r"(r[1]), "=r"(r[2]), "=r"(r[3]) : "r"(addr));
}
__device__ __forceinline__ void mma16816(float* c, const uint32_t* a, const uint32_t* b){
    asm volatile(
        "mma.sync.aligned.m16n8k16.row.col.f32.bf16.bf16.f32 "
        "{%0,%1,%2,%3}, {%4,%5,%6,%7}, {%8,%9}, {%0,%1,%2,%3};"
        : "+f"(c[0]), "+f"(c[1]), "+f"(c[2]), "+f"(c[3])
        : "r"(a[0]), "r"(a[1]), "r"(a[2]), "r"(a[3]), "r"(b[0]), "r"(b[1]));
}
__device__ __forceinline__ void cpa16(uint32_t dst, const void* src){
    asm volatile("cp.async.cg.shared.global [%0], [%1], 16;" :: "r"(dst), "l"(src));
}
#define CPA_COMMIT() asm volatile("cp.async.commit_group;" ::: "memory")
#define CPA_WAIT1()  asm volatile("cp.async.wait_group 1;" ::: "memory")
#define CPA_WAIT0()  asm volatile("cp.async.wait_group 0;" ::: "memory")

// slab: rows x 16 bf16 payload (32B), pitch 48B (conflict-free ldmatrix)
__device__ __forceinline__ void ldA(uint32_t a[4], uint32_t slab, int wm, int t){
    ldsm4(a, slab + (uint32_t)((wm + (t & 15))*48 + (t >> 4)*16));
}
__device__ __forceinline__ void ldB(uint32_t b[4], uint32_t slab, int nb16, int t){
    ldsm4(b, slab + (uint32_t)((nb16 + ((t >> 4) << 3) + (t & 7))*48 + ((t >> 3) & 1)*16));
}
__device__ __forceinline__ uint32_t packbf2(float a, float b){
    __nv_bfloat162 t = __halves2bfloat162(__float2bfloat16(a), __float2bfloat16(b));
    return *(uint32_t*)&t;
}

// -------------------- K0: split Wq|Wk|Wv|Wg into bf16 hi/lo ------------------
__global__ void conv_w_kernel(const float* __restrict__ Wq, const float* __restrict__ Wk,
                              const float* __restrict__ Wv, const float* __restrict__ Wg){
    int idx = blockIdx.x*256 + threadIdx.x;
    int n  = idx / 96;
    int kq = idx - n*96;
    int which = n / 384;
    int r = n - which*384;
    const float* W = (which == 0) ? Wq : (which == 1) ? Wk : (which == 2) ? Wv : Wg;
    float4 v = *(const float4*)(W + (size_t)r*CS + kq*4);
    float x[4] = {v.x, v.y, v.z, v.w};
    __nv_bfloat16 h[4], l[4];
#pragma unroll
    for (int e = 0; e < 4; e++){
        h[e] = __float2bfloat16(x[e]);
        l[e] = __float2bfloat16(x[e] - __bfloat162float(h[e]));
    }
    size_t o = (size_t)n*CS + kq*4;
    *(__nv_bfloat162*)(g_wh + o)     = __halves2bfloat162(h[0], h[1]);
    *(__nv_bfloat162*)(g_wh + o + 2) = __halves2bfloat162(h[2], h[3]);
    *(__nv_bfloat162*)(g_wl + o)     = __halves2bfloat162(l[0], l[1]);
    *(__nv_bfloat162*)(g_wl + o + 2) = __halves2bfloat162(l[2], l[3]);
}

// -------------------- K1: layernorm(single) -> bf16 hi/lo --------------------
__global__ void ln_single_kernel(const float* __restrict__ x,
                                 const float* __restrict__ g,
                                 const float* __restrict__ b){
    __shared__ float rs[4], rq[4];
    int i = blockIdx.x, t = threadIdx.x;     // 128 threads
    int lane = t & 31, w = t >> 5;
    float v[3];
#pragma unroll
    for (int e = 0; e < 3; e++) v[e] = x[i*CS + e*128 + t];
    float s = v[0] + v[1] + v[2];
    float q = v[0]*v[0] + v[1]*v[1] + v[2]*v[2];
    s = warp_sum(s); q = warp_sum(q);
    if (lane == 0){ rs[w] = s; rq[w] = q; }
    __syncthreads();
    s = rs[0] + rs[1] + rs[2] + rs[3];
    q = rq[0] + rq[1] + rq[2] + rq[3];
    float mu   = s * (1.f/CS);
    float var  = q * (1.f/CS) - mu*mu;
    float rstd = rsqrtf(var + 1e-5f);
#pragma unroll
    for (int e = 0; e < 3; e++){
        int c = e*128 + t;
        float y = (v[e] - mu) * rstd * g[c] + b[c];
        __nv_bfloat16 hh = __float2bfloat16(y);
        g_ah[i*CS + c] = hh;
        g_al[i*CS + c] = __float2bfloat16(y - __bfloat162float(hh));
    }
}

// -------------------- K2: layernorm(pair) + bias = zn @ Wb -------------------
// v5: thread handles 2 j's (j, j+128) -> gzw broadcast loads amortized 2x.
// 16-channel chunks staged in smem (pitch 17 floats: conflict-free scalar LDS).
__global__ void __launch_bounds__(128) ln_pair_bias_kernel(
                                    const float4* __restrict__ z4,
                                    const float* __restrict__ gz,
                                    const float* __restrict__ bz,
                                    const float* __restrict__ Wb){
    __shared__ float zs[256*17];        // [j][c] pitch 17 (16 ch + 1 pad)
    __shared__ float gzw[128*8];        // gz[c]*Wb[c][h]
    __shared__ float GB[16];            // G[8], B[8]
    const int tid = threadIdx.x;
    const int i   = blockIdx.y;
    const int jt0 = blockIdx.x * 256;

    for (int p = tid; p < 1024; p += 128){
        int c = p >> 3, h = p & 7;
        gzw[p] = gz[c] * Wb[c*8 + h];
    }
    __syncthreads();
    if (tid < 8){
        float G = 0.f, B = 0.f;
        for (int c = 0; c < 128; c++){
            G += gzw[c*8 + tid];
            B = fmaf(bz[c], Wb[c*8 + tid], B);
        }
        GB[tid] = G; GB[8 + tid] = B;
    }

    const float4* zbase = z4 + ((size_t)i*L + jt0)*32;

    // prefetch chunk 0: 256 rows x 4 float4 (16 channels), coalesced
    float4 r[8];
#pragma unroll
    for (int u = 0; u < 8; u++){
        int idx = tid + u*128;              // [0,1024)
        int j = idx >> 2, cq = idx & 3;
        r[u] = zbase[(size_t)j*32 + cq];
    }

    float s0 = 0.f, q0 = 0.f, s1 = 0.f, q1 = 0.f;
    float d0[8] = {0,0,0,0,0,0,0,0};
    float d1[8] = {0,0,0,0,0,0,0,0};

#pragma unroll
    for (int ch = 0; ch < 8; ch++){
        // stage current chunk
#pragma unroll
        for (int u = 0; u < 8; u++){
            int idx = tid + u*128;
            int j = idx >> 2, cq = idx & 3;
            float* p = zs + j*17 + cq*4;
            p[0] = r[u].x; p[1] = r[u].y; p[2] = r[u].z; p[3] = r[u].w;
        }
        // prefetch next chunk
        if (ch < 7){
#pragma unroll
            for (int u = 0; u < 8; u++){
                int idx = tid + u*128;
                int j = idx >> 2, cq = idx & 3;
                r[u] = zbase[(size_t)j*32 + (ch+1)*4 + cq];
            }
        }
        __syncthreads();
        const float* zr0 = zs + tid*17;
        const float* zr1 = zs + (tid+128)*17;
        const float* gw  = gzw + ch*16*8;
#pragma unroll
        for (int c = 0; c < 16; c++){
            float za = zr0[c];
            float zb = zr1[c];
            s0 += za; q0 = fmaf(za, za, q0);
            s1 += zb; q1 = fmaf(zb, zb, q1);
            float4 w0 = *(const float4*)(gw + c*8);
            float4 w1 = *(const float4*)(gw + c*8 + 4);
            d0[0] = fmaf(za, w0.x, d0[0]); d1[0] = fmaf(zb, w0.x, d1[0]);
            d0[1] = fmaf(za, w0.y, d0[1]); d1[1] = fmaf(zb, w0.y, d1[1]);
            d0[2] = fmaf(za, w0.z, d0[2]); d1[2] = fmaf(zb, w0.z, d1[2]);
            d0[3] = fmaf(za, w0.w, d0[3]); d1[3] = fmaf(zb, w0.w, d1[3]);
            d0[4] = fmaf(za, w1.x, d0[4]); d1[4] = fmaf(zb, w1.x, d1[4]);
            d0[5] = fmaf(za, w1.y, d0[5]); d1[5] = fmaf(zb, w1.y, d1[5]);
            d0[6] = fmaf(za, w1.z, d0[6]); d1[6] = fmaf(zb, w1.z, d1[6]);
            d0[7] = fmaf(za, w1.w, d0[7]); d1[7] = fmaf(zb, w1.w, d1[7]);
        }
        __syncthreads();
    }

    {
        float mu   = s0 * (1.f/128.f);
        float var  = q0 * (1.f/128.f) - mu*mu;
        float rstd = rsqrtf(var + 1e-5f);
        float nm   = -rstd * mu;
        size_t jg  = (size_t)i*L + jt0 + tid;
#pragma unroll
        for (int h = 0; h < 8; h++)
            g_bias[(size_t)h*LL + jg] = fmaf(rstd, d0[h], fmaf(nm, GB[h], GB[8+h]));
    }
    {
        float mu   = s1 * (1.f/128.f);
        float var  = q1 * (1.f/128.f) - mu*mu;
        float rstd = rsqrtf(var + 1e-5f);
        float nm   = -rstd * mu;
        size_t jg  = (size_t)i*L + jt0 + 128 + tid;
#pragma unroll
        for (int h = 0; h < 8; h++)
            g_bias[(size_t)h*LL + jg] = fmaf(rstd, d1[h], fmaf(nm, GB[h], GB[8+h]));
    }
}

// -------------------- K3: Q,K,V^T,Gate (pipelined mma) -----------------------
#define QCH 12288
__global__ void __launch_bounds__(256) qkvg_mma(){
    __shared__ __align__(16) char sm[2*QCH];
    const uint32_t sb = smem_u32(sm);
    const int tid = threadIdx.x, lane = tid & 31, wid = tid >> 5;
    const int wm16 = (wid & 3) * 16, wn32 = (wid >> 2) * 32;
    const int m0 = blockIdx.y * 64;
    const int ng = blockIdx.x * 64;

    float acc[4][4];
#pragma unroll
    for (int b = 0; b < 4; b++)
#pragma unroll
        for (int c = 0; c < 4; c++) acc[b][c] = 0.f;

    auto load = [&](int buf, int ch){
        int k = ch * 16;
#pragma unroll
        for (int u = 0; u < 2; u++){
            int idx = tid + u*256;
            int s = idx >> 7, rc = idx & 127, r = rc >> 1, c = rc & 1;
            const __nv_bfloat16* src =
                (s == 0) ? g_ah + (size_t)(m0+r)*CS + k + c*8 :
                (s == 1) ? g_al + (size_t)(m0+r)*CS + k + c*8 :
                (s == 2) ? g_wh + (size_t)(ng+r)*CS + k + c*8 :
                           g_wl + (size_t)(ng+r)*CS + k + c*8;
            cpa16(sb + buf*QCH + s*3072 + r*48 + c*16, src);
        }
        CPA_COMMIT();
    };

    load(0, 0);
    for (int ch = 0; ch < 24; ch++){
        if (ch + 1 < 24){ load((ch+1) & 1, ch+1); CPA_WAIT1(); }
        else CPA_WAIT0();
        __syncthreads();
        uint32_t base = sb + (ch & 1)*QCH;
        uint32_t ah[4], al[4], bh[2][4], bl[2][4];
        ldA(ah, base,        wm16, lane);
        ldA(al, base + 3072, wm16, lane);
#pragma unroll
        for (int pr = 0; pr < 2; pr++){
            ldB(bh[pr], base + 6144, wn32 + pr*16, lane);
            ldB(bl[pr], base + 9216, wn32 + pr*16, lane);
        }
#pragma unroll
        for (int nt = 0; nt < 4; nt++){
            const uint32_t* bhp = &bh[nt>>1][(nt&1)*2];
            const uint32_t* blp = &bl[nt>>1][(nt&1)*2];
            mma16816(acc[nt], ah, bhp);
            mma16816(acc[nt], al, bhp);
            mma16816(acc[nt], ah, blp);
        }
        __syncthreads();
    }

    const int which = ng / 384;
    const int nloc  = ng - which*384;
    const int rb = m0 + wm16 + (lane >> 2);
    const int cb = wn32 + (lane & 3)*2;
    if (which <= 1){
        __nv_bfloat16* PH = which ? g_kh : g_qh;
        __nv_bfloat16* PL = which ? g_kl : g_ql;
#pragma unroll
        for (int half = 0; half < 2; half++){
            int i = rb + half*8;
#pragma unroll
            for (int nt = 0; nt < 4; nt++){
                int cg = nloc + cb + nt*8;
                float v0 = acc[nt][half*2], v1 = acc[nt][half*2+1];
                __nv_bfloat16 h0 = __float2bfloat16(v0);
                __nv_bfloat16 h1 = __float2bfloat16(v1);
                __nv_bfloat16 l0 = __float2bfloat16(v0 - __bfloat162float(h0));
                __nv_bfloat16 l1 = __float2bfloat16(v1 - __bfloat162float(h1));
                *(__nv_bfloat162*)(PH + (size_t)i*CS + cg) = __halves2bfloat162(h0, h1);
                *(__nv_bfloat162*)(PL + (size_t)i*CS + cg) = __halves2bfloat162(l0, l1);
            }
        }
    } else if (which == 2){
#pragma unroll
        for (int half = 0; half < 2; half++){
            int i = rb + half*8;
#pragma unroll
            for (int nt = 0; nt < 4; nt++){
                int cg = nloc + cb + nt*8;
                float v0 = acc[nt][half*2], v1 = acc[nt][half*2+1];
                __nv_bfloat16 h0 = __float2bfloat16(v0);
                __nv_bfloat16 h1 = __float2bfloat16(v1);
                g_vth[(size_t)cg*L + i]     = h0;
                g_vth[(size_t)(cg+1)*L + i] = h1;
                g_vtl[(size_t)cg*L + i]     = __float2bfloat16(v0 - __bfloat162float(h0));
                g_vtl[(size_t)(cg+1)*L + i] = __float2bfloat16(v1 - __bfloat162float(h1));
            }
        }
    } else {
#pragma unroll
        for (int half = 0; half < 2; half++){
            int i = rb + half*8;
#pragma unroll
            for (int nt = 0; nt < 4; nt++){
                int cg = nloc + cb + nt*8;
                float2 v = make_float2(acc[nt][half*2], acc[nt][half*2+1]);
                *(float2*)(g_gate + (size_t)i*CS + cg) = v;
            }
        }
    }
}

// -------------------- K4: fused flash attention ------------------------------
// grid (jsplit=4, mtiles=12, h=8), 128 threads (4 warps x m16, full n=64).
// smem: K hi[0,9216) K lo[9216,18432) V hi[18432,27648) V lo[27648,36864)
__global__ void __launch_bounds__(128) attn_fused(){
    __shared__ __align__(16) char sm[36864];
    const uint32_t sb = smem_u32(sm);
    const int tid = threadIdx.x, lane = tid & 31, wid = tid >> 5;
    const int js = blockIdx.x;
    const int m0 = blockIdx.y * 64;
    const int h  = blockIdx.z;
    const int jb = js * 192;
    const float sc = 0.14433756729740643f;

    // --- stage Q tile through smem, keep A-fragments in registers ---
#pragma unroll
    for (int u = 0; u < 6; u++){
        int idx = tid + u*128;               // [0,768)
        int plane = idx / 384, rem = idx - plane*384;
        int s = rem >> 7, rc = rem & 127, r = rc >> 1, c = rc & 1;
        const __nv_bfloat16* src = (plane ? g_ql : g_qh)
            + (size_t)(m0+r)*CS + h*HD + s*16 + c*8;
        *(uint4*)(sm + plane*9216 + s*3072 + r*48 + c*16) = *(const uint4*)src;
    }
    __syncthreads();
    uint32_t qh[3][4], ql[3][4];
#pragma unroll
    for (int s = 0; s < 3; s++){
        ldA(qh[s], sb +        (uint32_t)(s*3072), wid*16, lane);
        ldA(ql[s], sb + 9216 + (uint32_t)(s*3072), wid*16, lane);
    }

    float mrow[2] = {-INFINITY, -INFINITY};
    float lrow[2] = {0.f, 0.f};
    float o[6][4];
#pragma unroll
    for (int dn = 0; dn < 6; dn++)
#pragma unroll
        for (int e = 0; e < 4; e++) o[dn][e] = 0.f;

    const int r0 = lane >> 2;                 // warp-local row (and +8)
    const int c0 = (lane & 3) * 2;

    for (int step = 0; step < 3; step++){
        int j0 = jb + step*64;
        __syncthreads();   // prior iteration's smem reads complete
        // load K tile (64 rows j x 48) hi/lo and V^T tile (48 rows d x 64 j) hi/lo
#pragma unroll
        for (int u = 0; u < 12; u++){
            int idx = tid + u*128;            // [0,1536)
            if (idx < 768){
                int plane = idx / 384, rem = idx - plane*384;
                int s = rem >> 7, rc = rem & 127, r = rc >> 1, c = rc & 1;
                const __nv_bfloat16* src = (plane ? g_kl : g_kh)
                    + (size_t)(j0+r)*CS + h*HD + s*16 + c*8;
                *(uint4*)(sm + plane*9216 + s*3072 + r*48 + c*16) = *(const uint4*)src;
            } else {
                int q2 = idx - 768;
                int plane = q2 / 384, rem = q2 - plane*384;
                int g = rem / 96, rc = rem - g*96, r = rc >> 1, c = rc & 1;
                const __nv_bfloat16* src = (plane ? g_vtl : g_vth)
                    + (size_t)(h*HD + r)*L + j0 + g*16 + c*8;
                *(uint4*)(sm + 18432 + plane*9216 + g*2304 + r*48 + c*16) = *(const uint4*)src;
            }
        }
        __syncthreads();

        // --- S = Q K^T (bf16-split, 3 terms) ---
        float s_[8][4];
#pragma unroll
        for (int nt = 0; nt < 8; nt++)
#pragma unroll
            for (int e = 0; e < 4; e++) s_[nt][e] = 0.f;
#pragma unroll
        for (int sl = 0; sl < 3; sl++){
            uint32_t bh[4][4], bl[4][4];
#pragma unroll
            for (int p = 0; p < 4; p++){
                ldB(bh[p], sb +        (uint32_t)(sl*3072), p*16, lane);
                ldB(bl[p], sb + 9216 + (uint32_t)(sl*3072), p*16, lane);
            }
#pragma unroll
            for (int nt = 0; nt < 8; nt++){
                const uint32_t* bhp = &bh[nt>>1][(nt&1)*2];
                const uint32_t* blp = &bl[nt>>1][(nt&1)*2];
                mma16816(s_[nt], qh[sl], bhp);
                mma16816(s_[nt], ql[sl], bhp);
                mma16816(s_[nt], qh[sl], blp);
            }
        }

        // --- add bias (direct from L2-resident g_bias) ---
#pragma unroll
        for (int nt = 0; nt < 8; nt++)
#pragma unroll
            for (int e = 0; e < 2; e++){
                int i = m0 + wid*16 + r0 + e*8;
                float2 b = *(const float2*)(g_bias + (size_t)h*LL + (size_t)i*L
                                            + j0 + nt*8 + c0);
                s_[nt][e*2]   = fmaf(s_[nt][e*2],   sc, b.x);
                s_[nt][e*2+1] = fmaf(s_[nt][e*2+1], sc, b.y);
            }

        // --- online softmax (rows fully inside warp quad) ---
#pragma unroll
        for (int e = 0; e < 2; e++){
            float mx = -INFINITY;
#pragma unroll
            for (int nt = 0; nt < 8; nt++)
                mx = fmaxf(mx, fmaxf(s_[nt][e*2], s_[nt][e*2+1]));
            mx = fmaxf(mx, __shfl_xor_sync(0xffffffffu, mx, 1));
            mx = fmaxf(mx, __shfl_xor_sync(0xffffffffu, mx, 2));
            float mn = fmaxf(mrow[e], mx);
            float alpha = __expf(mrow[e] - mn);
            mrow[e] = mn;
            float sum = 0.f;
#pragma unroll
            for (int nt = 0; nt < 8; nt++){
                float p0 = __expf(s_[nt][e*2]   - mn);
                float p1 = __expf(s_[nt][e*2+1] - mn);
                s_[nt][e*2] = p0; s_[nt][e*2+1] = p1;
                sum += p0 + p1;
            }
            sum += __shfl_xor_sync(0xffffffffu, sum, 1);
            sum += __shfl_xor_sync(0xffffffffu, sum, 2);
            lrow[e] = lrow[e]*alpha + sum;
#pragma unroll
            for (int dn = 0; dn < 6; dn++){
                o[dn][e*2]   *= alpha;
                o[dn][e*2+1] *= alpha;
            }
        }

        // --- O += P V  (P from C-frag -> A-frag identity, hi/lo split) ---
#pragma unroll
        for (int g = 0; g < 4; g++){
            uint32_t aH[4], aL[4];
#pragma unroll
            for (int half = 0; half < 2; half++){
                int nt = 2*g + half;
#pragma unroll
                for (int e = 0; e < 2; e++){
                    float p0 = s_[nt][e*2], p1 = s_[nt][e*2+1];
                    uint32_t hi = packbf2(p0, p1);
                    __nv_bfloat162 hv = *(__nv_bfloat162*)&hi;
                    uint32_t lo = packbf2(p0 - __bfloat162float(hv.x),
                                          p1 - __bfloat162float(hv.y));
                    aH[half*2 + e] = hi;
                    aL[half*2 + e] = lo;
                }
            }
            uint32_t vh[3][4], vl[3][4];
#pragma unroll
            for (int q = 0; q < 3; q++){
                ldB(vh[q], sb + 18432 + (uint32_t)(g*2304), q*16, lane);
                ldB(vl[q], sb + 27648 + (uint32_t)(g*2304), q*16, lane);
            }
#pragma unroll
            for (int dn = 0; dn < 6; dn++){
                const uint32_t* vhp = &vh[dn>>1][(dn&1)*2];
                const uint32_t* vlp = &vl[dn>>1][(dn&1)*2];
                mma16816(o[dn], aH, vhp);
                mma16816(o[dn], aL, vhp);
                mma16816(o[dn], aH, vlp);
            }
        }
    }

    // --- write unnormalized O + stats ---
#pragma unroll
    for (int e = 0; e < 2; e++){
        int i = m0 + wid*16 + r0 + e*8;
        float* op = g_opart + (size_t)js*OPS + (size_t)i*CS + h*HD;
#pragma unroll
        for (int dn = 0; dn < 6; dn++)
            *(float2*)(op + dn*8 + c0) = make_float2(o[dn][e*2], o[dn][e*2+1]);
        if ((lane & 3) == 0)
            g_stat[js*NH*L + h*L + i] = make_float2(mrow[e], lrow[e]);
    }
}

// -------------------- K5: out = single + sigmoid(gate+bg)*(O@Wo^T+bo) -------
// A = softmax-combined O from NSPLIT splits. 64x64 tile, BK=32, 128 threads.
__global__ void __launch_bounds__(128) final_kernel(
        const float* __restrict__ Wo, const float* __restrict__ bo,
        const float* __restrict__ single, const float* __restrict__ bg,
        float* __restrict__ out){
    __shared__ float As[32*68];
    __shared__ float Bs[32*68];
    __shared__ float wsm[64][8][NSPLIT];    // combine weights per (row, head)
    const int tid = threadIdx.x;
    const int tx  = tid % 16, ty = tid / 16;   // TN=4, TM=8
    const int m0 = blockIdx.y*64, n0 = blockIdx.x*64;

    // precompute split-combine weights
    for (int p = tid; p < 64*8; p += 128){
        int row = p >> 3, h = p & 7;
        int gi = m0 + row;
        float2 st[NSPLIT];
        float M = -INFINITY;
#pragma unroll
        for (int s = 0; s < NSPLIT; s++){
            st[s] = g_stat[s*NH*L + h*L + gi];
            M = fmaxf(M, st[s].x);
        }
        float w[NSPLIT], den = 0.f;
#pragma unroll
        for (int s = 0; s < NSPLIT; s++){
            w[s] = __expf(st[s].x - M);
            den = fmaf(w[s], st[s].y, den);
        }
        float inv = 1.f / den;
#pragma unroll
        for (int s = 0; s < NSPLIT; s++) wsm[row][h][s] = w[s]*inv;
    }
    __syncthreads();

    float acc[8][4];
#pragma unroll
    for (int i = 0; i < 8; i++)
#pragma unroll
        for (int j = 0; j < 4; j++) acc[i][j] = 0.f;

    for (int kt = 0; kt < CS; kt += 32){
#pragma unroll
        for (int u = 0; u < 4; u++){
            int t4 = tid + u*128;             // AF4 = 64*8 = 512
            int row = t4 >> 3, kq = t4 & 7;
            int c = kt + kq*4;
            int h = c / HD;
            int gi = m0 + row;
            const float* p = g_opart + (size_t)gi*CS + c;
            float4 v = make_float4(0.f, 0.f, 0.f, 0.f);
#pragma unroll
            for (int s = 0; s < NSPLIT; s++){
                float ws = wsm[row][h][s];
                float4 vs = *(const float4*)(p + (size_t)s*OPS);
                v.x = fmaf(ws, vs.x, v.x); v.y = fmaf(ws, vs.y, v.y);
                v.z = fmaf(ws, vs.z, v.z); v.w = fmaf(ws, vs.w, v.w);
            }
            As[(kq*4+0)*68+row] = v.x; As[(kq*4+1)*68+row] = v.y;
            As[(kq*4+2)*68+row] = v.z; As[(kq*4+3)*68+row] = v.w;
        }
#pragma unroll
        for (int u = 0; u < 4; u++){
            int t4 = tid + u*128;             // BF4 = 64*8 = 512
            int row = t4 >> 3, kq = t4 & 7;
            float4 v = *(const float4*)(Wo + (size_t)(n0 + row)*CS + kt + kq*4);
            Bs[(kq*4+0)*68+row] = v.x; Bs[(kq*4+1)*68+row] = v.y;
            Bs[(kq*4+2)*68+row] = v.z; Bs[(kq*4+3)*68+row] = v.w;
        }
        __syncthreads();
#pragma unroll
        for (int kk = 0; kk < 32; kk++){
            float af[8], bf[4];
            *(float4*)&af[0] = *(const float4*)&As[kk*68 + ty*8];
            *(float4*)&af[4] = *(const float4*)&As[kk*68 + ty*8 + 4];
            *(float4*)&bf[0] = *(const float4*)&Bs[kk*68 + tx*4];
#pragma unroll
            for (int i = 0; i < 8; i++)
#pragma unroll
                for (int j = 0; j < 4; j++)
                    acc[i][j] = fmaf(af[i], bf[j], acc[i][j]);
        }
        __syncthreads();
    }

#pragma unroll
    for (int i = 0; i < 8; i++){
        int row = m0 + ty*8 + i;
#pragma unroll
        for (int j = 0; j < 4; j++){
            int col = n0 + tx*4 + j;
            float y  = acc[i][j] + bo[col];
            float gp = g_gate[(size_t)row*CS + col] + bg[col];
            float gg = 1.f / (1.f + __expf(-gp));
            out[(size_t)row*CS + col] = single[(size_t)row*CS + col] + gg * y;
        }
    }
}

// -------------------- launch --------------------
extern "C" void kernel_launch(void* const* d_in, const int* in_sizes, int n_in,
                              void* d_out, int out_size){
    const float* single = (const float*)d_in[0];
    const float* pair   = (const float*)d_in[1];
    const float* gs     = (const float*)d_in[2];
    const float* bs     = (const float*)d_in[3];
    const float* gz     = (const float*)d_in[4];
    const float* bz     = (const float*)d_in[5];
    const float* Wq     = (const float*)d_in[6];
    const float* Wk     = (const float*)d_in[7];
    const float* Wv     = (const float*)d_in[8];
    const float* Wb     = (const float*)d_in[9];
    const float* Wo     = (const float*)d_in[10];
    const float* bo     = (const float*)d_in[11];
    const float* Wg     = (const float*)d_in[12];
    const float* bg     = (const float*)d_in[13];
    float* out = (float*)d_out;

    // ln_pair_bias kept in 4th slot (profiler captures launch #4).
    conv_w_kernel<<<576, 256>>>(Wq, Wk, Wv, Wg);
    ln_single_kernel<<<L, 128>>>(single, gs, bs);
    qkvg_mma<<<dim3(1536/64, L/64), 256>>>();
    ln_pair_bias_kernel<<<dim3(3, L), 128>>>((const float4*)pair, gz, bz, Wb);
    attn_fused<<<dim3(NSPLIT, L/64, NH), 128>>>();
    final_kernel<<<dim3(CS/64, L/64), 128>>>(Wo, bo, single, bg, out);
}

// round 15
// speedup vs baseline: 1.1404x; 1.1404x over previous
#include <cuda_runtime.h>
#include <cuda_bf16.h>
#include <cstdint>
#include <math.h>

// AttentionWithPairBias: B=1, L=768, C_S=384, C_Z=128, H=8, HD=48
#define L 768
#define CS 384
#define NH 8
#define HD 48
#define LL (L*L)
#define OPS (L*CS)
#define NSPLIT 4

// -------------------- scratch (device globals; no allocs) --------------------
__device__ float g_bias[(size_t)NH*LL];  // pair bias (fp32), read by attn
__device__ float g_gate[L*CS];
__device__ float g_opart[NSPLIT*OPS];    // unnormalized O per j-split
__device__ float2 g_stat[NSPLIT*NH*L];   // per split: (m, l) per (h, i)
__device__ __nv_bfloat16 g_ah[L*CS], g_al[L*CS];         // layernorm(single) hi/lo
__device__ __nv_bfloat16 g_wh[4*CS*CS], g_wl[4*CS*CS];   // Wq|Wk|Wv|Wg rows, hi/lo
__device__ __nv_bfloat16 g_qh[L*CS], g_ql[L*CS];         // Q hi/lo
__device__ __nv_bfloat16 g_kh[L*CS], g_kl[L*CS];         // K hi/lo
__device__ __nv_bfloat16 g_vth[CS*L], g_vtl[CS*L];       // V^T hi/lo: [d][j]

// -------------------- warp helpers --------------------
__device__ __forceinline__ float warp_sum(float v){
#pragma unroll
    for (int o = 16; o; o >>= 1) v += __shfl_xor_sync(0xffffffffu, v, o);
    return v;
}

// -------------------- mma.sync / ldmatrix / cp.async (plain PTX, sm_80+) ----
__device__ __forceinline__ uint32_t smem_u32(const void* p){
    uint32_t a;
    asm("{ .reg .u64 t; cvta.to.shared.u64 t, %1; cvt.u32.u64 %0, t; }" : "=r"(a) : "l"(p));
    return a;
}
__device__ __forceinline__ void ldsm4(uint32_t* r, uint32_t addr){
    asm volatile("ldmatrix.sync.aligned.m8n8.x4.shared.b16 {%0,%1,%2,%3}, [%4];"
        : "=r"(r[0]), "=r"(r[1]), "=r"(r[2]), "=r"(r[3]) : "r"(addr));
}
__device__ __forceinline__ void mma16816(float* c, const uint32_t* a, const uint32_t* b){
    asm volatile(
        "mma.sync.aligned.m16n8k16.row.col.f32.bf16.bf16.f32 "
        "{%0,%1,%2,%3}, {%4,%5,%6,%7}, {%8,%9}, {%0,%1,%2,%3};"
        : "+f"(c[0]), "+f"(c[1]), "+f"(c[2]), "+f"(c[3])
        : "r"(a[0]), "r"(a[1]), "r"(a[2]), "r"(a[3]), "r"(b[0]), "r"(b[1]));
}
__device__ __forceinline__ void cpa16(uint32_t dst, const void* src){
    asm volatile("cp.async.cg.shared.global [%0], [%1], 16;" :: "r"(dst), "l"(src));
}
#define CPA_COMMIT() asm volatile("cp.async.commit_group;" ::: "memory")
#define CPA_WAIT1()  asm volatile("cp.async.wait_group 1;" ::: "memory")
#define CPA_WAIT0()  asm volatile("cp.async.wait_group 0;" ::: "memory")

// slab: rows x 16 bf16 payload (32B), pitch 48B (conflict-free ldmatrix)
__device__ __forceinline__ void ldA(uint32_t a[4], uint32_t slab, int wm, int t){
    ldsm4(a, slab + (uint32_t)((wm + (t & 15))*48 + (t >> 4)*16));
}
__device__ __forceinline__ void ldB(uint32_t b[4], uint32_t slab, int nb16, int t){
    ldsm4(b, slab + (uint32_t)((nb16 + ((t >> 4) << 3) + (t & 7))*48 + ((t >> 3) & 1)*16));
}
__device__ __forceinline__ uint32_t packbf2(float a, float b){
    __nv_bfloat162 t = __halves2bfloat162(__float2bfloat16(a), __float2bfloat16(b));
    return *(uint32_t*)&t;
}

// -------------------- K0: split Wq|Wk|Wv|Wg into bf16 hi/lo ------------------
__global__ void conv_w_kernel(const float* __restrict__ Wq, const float* __restrict__ Wk,
                              const float* __restrict__ Wv, const float* __restrict__ Wg){
    int idx = blockIdx.x*256 + threadIdx.x;
    int n  = idx / 96;
    int kq = idx - n*96;
    int which = n / 384;
    int r = n - which*384;
    const float* W = (which == 0) ? Wq : (which == 1) ? Wk : (which == 2) ? Wv : Wg;
    float4 v = *(const float4*)(W + (size_t)r*CS + kq*4);
    float x[4] = {v.x, v.y, v.z, v.w};
    __nv_bfloat16 h[4], l[4];
#pragma unroll
    for (int e = 0; e < 4; e++){
        h[e] = __float2bfloat16(x[e]);
        l[e] = __float2bfloat16(x[e] - __bfloat162float(h[e]));
    }
    size_t o = (size_t)n*CS + kq*4;
    *(__nv_bfloat162*)(g_wh + o)     = __halves2bfloat162(h[0], h[1]);
    *(__nv_bfloat162*)(g_wh + o + 2) = __halves2bfloat162(h[2], h[3]);
    *(__nv_bfloat162*)(g_wl + o)     = __halves2bfloat162(l[0], l[1]);
    *(__nv_bfloat162*)(g_wl + o + 2) = __halves2bfloat162(l[2], l[3]);
}

// -------------------- K1: layernorm(single) -> bf16 hi/lo --------------------
__global__ void ln_single_kernel(const float* __restrict__ x,
                                 const float* __restrict__ g,
                                 const float* __restrict__ b){
    __shared__ float rs[4], rq[4];
    int i = blockIdx.x, t = threadIdx.x;     // 128 threads
    int lane = t & 31, w = t >> 5;
    float v[3];
#pragma unroll
    for (int e = 0; e < 3; e++) v[e] = x[i*CS + e*128 + t];
    float s = v[0] + v[1] + v[2];
    float q = v[0]*v[0] + v[1]*v[1] + v[2]*v[2];
    s = warp_sum(s); q = warp_sum(q);
    if (lane == 0){ rs[w] = s; rq[w] = q; }
    __syncthreads();
    s = rs[0] + rs[1] + rs[2] + rs[3];
    q = rq[0] + rq[1] + rq[2] + rq[3];
    float mu   = s * (1.f/CS);
    float var  = q * (1.f/CS) - mu*mu;
    float rstd = rsqrtf(var + 1e-5f);
#pragma unroll
    for (int e = 0; e < 3; e++){
        int c = e*128 + t;
        float y = (v[e] - mu) * rstd * g[c] + b[c];
        __nv_bfloat16 hh = __float2bfloat16(y);
        g_ah[i*CS + c] = hh;
        g_al[i*CS + c] = __float2bfloat16(y - __bfloat162float(hh));
    }
}

// -------------------- K2: layernorm(pair) + bias = zn @ Wb -------------------
// v6: thread-per-j, cp.async.cg staging (no LDG->reg->STS round trip), XOR-
// swizzled pitch-32 rows so compute reads are conflict-free LDS.128.
// 128 j per block, 4 chunks of 32 channels, 2-deep pipeline.
__global__ void __launch_bounds__(128) ln_pair_bias_kernel(
                                    const float4* __restrict__ z4,
                                    const float* __restrict__ gz,
                                    const float* __restrict__ bz,
                                    const float* __restrict__ Wb){
    __shared__ __align__(16) float zs[2*128*32];  // 2 bufs x 128 rows x 128B
    __shared__ float gzw[128*8];
    __shared__ float GB[16];
    const uint32_t sbz = smem_u32(zs);
    const int tid = threadIdx.x;
    const int i   = blockIdx.y;
    const int jt0 = blockIdx.x * 128;

    for (int p = tid; p < 1024; p += 128){
        int c = p >> 3, h = p & 7;
        gzw[p] = gz[c] * Wb[c*8 + h];
    }
    __syncthreads();
    if (tid < 8){
        float G = 0.f, B = 0.f;
        for (int c = 0; c < 128; c++){
            G += gzw[c*8 + tid];
            B = fmaf(bz[c], Wb[c*8 + tid], B);
        }
        GB[tid] = G; GB[8 + tid] = B;
    }

    const float4* zbase = z4 + ((size_t)i*L + jt0)*32;

    // async-load one 32-channel chunk into buffer buf (swizzled chunk slots)
    auto load = [&](int buf, int ch){
#pragma unroll
        for (int u = 0; u < 8; u++){
            int idx = tid + u*128;           // [0,1024): 128 rows x 8 float4
            int j = idx >> 3, cq = idx & 7;
            cpa16(sbz + (uint32_t)(buf*16384 + j*128 + ((cq ^ (j & 7))*16)),
                  zbase + (size_t)j*32 + ch*8 + cq);
        }
        CPA_COMMIT();
    };

    load(0, 0);
    float s = 0.f, q = 0.f;
    float d[8] = {0,0,0,0,0,0,0,0};

#pragma unroll
    for (int ch = 0; ch < 4; ch++){
        if (ch + 1 < 4){ load((ch+1) & 1, ch+1); CPA_WAIT1(); }
        else CPA_WAIT0();
        __syncthreads();
        const float* zrow = zs + (ch & 1)*4096 + tid*32;
        const int sw = tid & 7;
        const float* gw = gzw + ch*32*8;
#pragma unroll
        for (int c4 = 0; c4 < 8; c4++){
            float4 zv = *(const float4*)(zrow + ((c4 ^ sw) << 2));
            // note: slot (c4^sw) holds channels ((c4^sw)^sw)*4 = c4*4 ✓
            float z0 = zv.x, z1 = zv.y, z2 = zv.z, z3 = zv.w;
            s += z0 + z1 + z2 + z3;
            q = fmaf(z0,z0, fmaf(z1,z1, fmaf(z2,z2, fmaf(z3,z3, q))));
            const float* g0 = gw + c4*32;     // 4 channels x 8 heads
#pragma unroll
            for (int e = 0; e < 4; e++){
                float z = (e==0)?z0:(e==1)?z1:(e==2)?z2:z3;
                float4 w0 = *(const float4*)(g0 + e*8);
                float4 w1 = *(const float4*)(g0 + e*8 + 4);
                d[0] = fmaf(z, w0.x, d[0]);
                d[1] = fmaf(z, w0.y, d[1]);
                d[2] = fmaf(z, w0.z, d[2]);
                d[3] = fmaf(z, w0.w, d[3]);
                d[4] = fmaf(z, w1.x, d[4]);
                d[5] = fmaf(z, w1.y, d[5]);
                d[6] = fmaf(z, w1.z, d[6]);
                d[7] = fmaf(z, w1.w, d[7]);
            }
        }
        __syncthreads();
    }

    float mu   = s * (1.f/128.f);
    float var  = q * (1.f/128.f) - mu*mu;
    float rstd = rsqrtf(var + 1e-5f);
    float nm   = -rstd * mu;
    size_t jg  = (size_t)i*L + jt0 + tid;
#pragma unroll
    for (int h = 0; h < 8; h++)
        g_bias[(size_t)h*LL + jg] = fmaf(rstd, d[h], fmaf(nm, GB[h], GB[8+h]));
}

// -------------------- K3: Q,K,V^T,Gate (pipelined mma) -----------------------
#define QCH 12288
__global__ void __launch_bounds__(256) qkvg_mma(){
    __shared__ __align__(16) char sm[2*QCH];
    const uint32_t sb = smem_u32(sm);
    const int tid = threadIdx.x, lane = tid & 31, wid = tid >> 5;
    const int wm16 = (wid & 3) * 16, wn32 = (wid >> 2) * 32;
    const int m0 = blockIdx.y * 64;
    const int ng = blockIdx.x * 64;

    float acc[4][4];
#pragma unroll
    for (int b = 0; b < 4; b++)
#pragma unroll
        for (int c = 0; c < 4; c++) acc[b][c] = 0.f;

    auto load = [&](int buf, int ch){
        int k = ch * 16;
#pragma unroll
        for (int u = 0; u < 2; u++){
            int idx = tid + u*256;
            int s = idx >> 7, rc = idx & 127, r = rc >> 1, c = rc & 1;
            const __nv_bfloat16* src =
                (s == 0) ? g_ah + (size_t)(m0+r)*CS + k + c*8 :
                (s == 1) ? g_al + (size_t)(m0+r)*CS + k + c*8 :
                (s == 2) ? g_wh + (size_t)(ng+r)*CS + k + c*8 :
                           g_wl + (size_t)(ng+r)*CS + k + c*8;
            cpa16(sb + buf*QCH + s*3072 + r*48 + c*16, src);
        }
        CPA_COMMIT();
    };

    load(0, 0);
    for (int ch = 0; ch < 24; ch++){
        if (ch + 1 < 24){ load((ch+1) & 1, ch+1); CPA_WAIT1(); }
        else CPA_WAIT0();
        __syncthreads();
        uint32_t base = sb + (ch & 1)*QCH;
        uint32_t ah[4], al[4], bh[2][4], bl[2][4];
        ldA(ah, base,        wm16, lane);
        ldA(al, base + 3072, wm16, lane);
#pragma unroll
        for (int pr = 0; pr < 2; pr++){
            ldB(bh[pr], base + 6144, wn32 + pr*16, lane);
            ldB(bl[pr], base + 9216, wn32 + pr*16, lane);
        }
#pragma unroll
        for (int nt = 0; nt < 4; nt++){
            const uint32_t* bhp = &bh[nt>>1][(nt&1)*2];
            const uint32_t* blp = &bl[nt>>1][(nt&1)*2];
            mma16816(acc[nt], ah, bhp);
            mma16816(acc[nt], al, bhp);
            mma16816(acc[nt], ah, blp);
        }
        __syncthreads();
    }

    const int which = ng / 384;
    const int nloc  = ng - which*384;
    const int rb = m0 + wm16 + (lane >> 2);
    const int cb = wn32 + (lane & 3)*2;
    if (which <= 1){
        __nv_bfloat16* PH = which ? g_kh : g_qh;
        __nv_bfloat16* PL = which ? g_kl : g_ql;
#pragma unroll
        for (int half = 0; half < 2; half++){
            int i = rb + half*8;
#pragma unroll
            for (int nt = 0; nt < 4; nt++){
                int cg = nloc + cb + nt*8;
                float v0 = acc[nt][half*2], v1 = acc[nt][half*2+1];
                __nv_bfloat16 h0 = __float2bfloat16(v0);
                __nv_bfloat16 h1 = __float2bfloat16(v1);
                __nv_bfloat16 l0 = __float2bfloat16(v0 - __bfloat162float(h0));
                __nv_bfloat16 l1 = __float2bfloat16(v1 - __bfloat162float(h1));
                *(__nv_bfloat162*)(PH + (size_t)i*CS + cg) = __halves2bfloat162(h0, h1);
                *(__nv_bfloat162*)(PL + (size_t)i*CS + cg) = __halves2bfloat162(l0, l1);
            }
        }
    } else if (which == 2){
#pragma unroll
        for (int half = 0; half < 2; half++){
            int i = rb + half*8;
#pragma unroll
            for (int nt = 0; nt < 4; nt++){
                int cg = nloc + cb + nt*8;
                float v0 = acc[nt][half*2], v1 = acc[nt][half*2+1];
                __nv_bfloat16 h0 = __float2bfloat16(v0);
                __nv_bfloat16 h1 = __float2bfloat16(v1);
                g_vth[(size_t)cg*L + i]     = h0;
                g_vth[(size_t)(cg+1)*L + i] = h1;
                g_vtl[(size_t)cg*L + i]     = __float2bfloat16(v0 - __bfloat162float(h0));
                g_vtl[(size_t)(cg+1)*L + i] = __float2bfloat16(v1 - __bfloat162float(h1));
            }
        }
    } else {
#pragma unroll
        for (int half = 0; half < 2; half++){
            int i = rb + half*8;
#pragma unroll
            for (int nt = 0; nt < 4; nt++){
                int cg = nloc + cb + nt*8;
                float2 v = make_float2(acc[nt][half*2], acc[nt][half*2+1]);
                *(float2*)(g_gate + (size_t)i*CS + cg) = v;
            }
        }
    }
}

// -------------------- K4: fused flash attention ------------------------------
__global__ void __launch_bounds__(128) attn_fused(){
    __shared__ __align__(16) char sm[36864];
    const uint32_t sb = smem_u32(sm);
    const int tid = threadIdx.x, lane = tid & 31, wid = tid >> 5;
    const int js = blockIdx.x;
    const int m0 = blockIdx.y * 64;
    const int h  = blockIdx.z;
    const int jb = js * 192;
    const float sc = 0.14433756729740643f;

#pragma unroll
    for (int u = 0; u < 6; u++){
        int idx = tid + u*128;
        int plane = idx / 384, rem = idx - plane*384;
        int s = rem >> 7, rc = rem & 127, r = rc >> 1, c = rc & 1;
        const __nv_bfloat16* src = (plane ? g_ql : g_qh)
            + (size_t)(m0+r)*CS + h*HD + s*16 + c*8;
        *(uint4*)(sm + plane*9216 + s*3072 + r*48 + c*16) = *(const uint4*)src;
    }
    __syncthreads();
    uint32_t qh[3][4], ql[3][4];
#pragma unroll
    for (int s = 0; s < 3; s++){
        ldA(qh[s], sb +        (uint32_t)(s*3072), wid*16, lane);
        ldA(ql[s], sb + 9216 + (uint32_t)(s*3072), wid*16, lane);
    }

    float mrow[2] = {-INFINITY, -INFINITY};
    float lrow[2] = {0.f, 0.f};
    float o[6][4];
#pragma unroll
    for (int dn = 0; dn < 6; dn++)
#pragma unroll
        for (int e = 0; e < 4; e++) o[dn][e] = 0.f;

    const int r0 = lane >> 2;
    const int c0 = (lane & 3) * 2;

    for (int step = 0; step < 3; step++){
        int j0 = jb + step*64;
        __syncthreads();
#pragma unroll
        for (int u = 0; u < 12; u++){
            int idx = tid + u*128;
            if (idx < 768){
                int plane = idx / 384, rem = idx - plane*384;
                int s = rem >> 7, rc = rem & 127, r = rc >> 1, c = rc & 1;
                const __nv_bfloat16* src = (plane ? g_kl : g_kh)
                    + (size_t)(j0+r)*CS + h*HD + s*16 + c*8;
                *(uint4*)(sm + plane*9216 + s*3072 + r*48 + c*16) = *(const uint4*)src;
            } else {
                int q2 = idx - 768;
                int plane = q2 / 384, rem = q2 - plane*384;
                int g = rem / 96, rc = rem - g*96, r = rc >> 1, c = rc & 1;
                const __nv_bfloat16* src = (plane ? g_vtl : g_vth)
                    + (size_t)(h*HD + r)*L + j0 + g*16 + c*8;
                *(uint4*)(sm + 18432 + plane*9216 + g*2304 + r*48 + c*16) = *(const uint4*)src;
            }
        }
        __syncthreads();

        float s_[8][4];
#pragma unroll
        for (int nt = 0; nt < 8; nt++)
#pragma unroll
            for (int e = 0; e < 4; e++) s_[nt][e] = 0.f;
#pragma unroll
        for (int sl = 0; sl < 3; sl++){
            uint32_t bh[4][4], bl[4][4];
#pragma unroll
            for (int p = 0; p < 4; p++){
                ldB(bh[p], sb +        (uint32_t)(sl*3072), p*16, lane);
                ldB(bl[p], sb + 9216 + (uint32_t)(sl*3072), p*16, lane);
            }
#pragma unroll
            for (int nt = 0; nt < 8; nt++){
                const uint32_t* bhp = &bh[nt>>1][(nt&1)*2];
                const uint32_t* blp = &bl[nt>>1][(nt&1)*2];
                mma16816(s_[nt], qh[sl], bhp);
                mma16816(s_[nt], ql[sl], bhp);
                mma16816(s_[nt], qh[sl], blp);
            }
        }

#pragma unroll
        for (int nt = 0; nt < 8; nt++)
#pragma unroll
            for (int e = 0; e < 2; e++){
                int i = m0 + wid*16 + r0 + e*8;
                float2 b = *(const float2*)(g_bias + (size_t)h*LL + (size_t)i*L
                                            + j0 + nt*8 + c0);
                s_[nt][e*2]   = fmaf(s_[nt][e*2],   sc, b.x);
                s_[nt][e*2+1] = fmaf(s_[nt][e*2+1], sc, b.y);
            }

#pragma unroll
        for (int e = 0; e < 2; e++){
            float mx = -INFINITY;
#pragma unroll
            for (int nt = 0; nt < 8; nt++)
                mx = fmaxf(mx, fmaxf(s_[nt][e*2], s_[nt][e*2+1]));
            mx = fmaxf(mx, __shfl_xor_sync(0xffffffffu, mx, 1));
            mx = fmaxf(mx, __shfl_xor_sync(0xffffffffu, mx, 2));
            float mn = fmaxf(mrow[e], mx);
            float alpha = __expf(mrow[e] - mn);
            mrow[e] = mn;
            float sum = 0.f;
#pragma unroll
            for (int nt = 0; nt < 8; nt++){
                float p0 = __expf(s_[nt][e*2]   - mn);
                float p1 = __expf(s_[nt][e*2+1] - mn);
                s_[nt][e*2] = p0; s_[nt][e*2+1] = p1;
                sum += p0 + p1;
            }
            sum += __shfl_xor_sync(0xffffffffu, sum, 1);
            sum += __shfl_xor_sync(0xffffffffu, sum, 2);
            lrow[e] = lrow[e]*alpha + sum;
#pragma unroll
            for (int dn = 0; dn < 6; dn++){
                o[dn][e*2]   *= alpha;
                o[dn][e*2+1] *= alpha;
            }
        }

#pragma unroll
        for (int g = 0; g < 4; g++){
            uint32_t aH[4], aL[4];
#pragma unroll
            for (int half = 0; half < 2; half++){
                int nt = 2*g + half;
#pragma unroll
                for (int e = 0; e < 2; e++){
                    float p0 = s_[nt][e*2], p1 = s_[nt][e*2+1];
                    uint32_t hi = packbf2(p0, p1);
                    __nv_bfloat162 hv = *(__nv_bfloat162*)&hi;
                    uint32_t lo = packbf2(p0 - __bfloat162float(hv.x),
                                          p1 - __bfloat162float(hv.y));
                    aH[half*2 + e] = hi;
                    aL[half*2 + e] = lo;
                }
            }
            uint32_t vh[3][4], vl[3][4];
#pragma unroll
            for (int q = 0; q < 3; q++){
                ldB(vh[q], sb + 18432 + (uint32_t)(g*2304), q*16, lane);
                ldB(vl[q], sb + 27648 + (uint32_t)(g*2304), q*16, lane);
            }
#pragma unroll
            for (int dn = 0; dn < 6; dn++){
                const uint32_t* vhp = &vh[dn>>1][(dn&1)*2];
                const uint32_t* vlp = &vl[dn>>1][(dn&1)*2];
                mma16816(o[dn], aH, vhp);
                mma16816(o[dn], aL, vhp);
                mma16816(o[dn], aH, vlp);
            }
        }
    }

#pragma unroll
    for (int e = 0; e < 2; e++){
        int i = m0 + wid*16 + r0 + e*8;
        float* op = g_opart + (size_t)js*OPS + (size_t)i*CS + h*HD;
#pragma unroll
        for (int dn = 0; dn < 6; dn++)
            *(float2*)(op + dn*8 + c0) = make_float2(o[dn][e*2], o[dn][e*2+1]);
        if ((lane & 3) == 0)
            g_stat[js*NH*L + h*L + i] = make_float2(mrow[e], lrow[e]);
    }
}

// -------------------- K5: out = single + sigmoid(gate+bg)*(O@Wo^T+bo) -------
__global__ void __launch_bounds__(128) final_kernel(
        const float* __restrict__ Wo, const float* __restrict__ bo,
        const float* __restrict__ single, const float* __restrict__ bg,
        float* __restrict__ out){
    __shared__ float As[32*68];
    __shared__ float Bs[32*68];
    __shared__ float wsm[64][8][NSPLIT];
    const int tid = threadIdx.x;
    const int tx  = tid % 16, ty = tid / 16;
    const int m0 = blockIdx.y*64, n0 = blockIdx.x*64;

    for (int p = tid; p < 64*8; p += 128){
        int row = p >> 3, h = p & 7;
        int gi = m0 + row;
        float2 st[NSPLIT];
        float M = -INFINITY;
#pragma unroll
        for (int s = 0; s < NSPLIT; s++){
            st[s] = g_stat[s*NH*L + h*L + gi];
            M = fmaxf(M, st[s].x);
        }
        float w[NSPLIT], den = 0.f;
#pragma unroll
        for (int s = 0; s < NSPLIT; s++){
            w[s] = __expf(st[s].x - M);
            den = fmaf(w[s], st[s].y, den);
        }
        float inv = 1.f / den;
#pragma unroll
        for (int s = 0; s < NSPLIT; s++) wsm[row][h][s] = w[s]*inv;
    }
    __syncthreads();

    float acc[8][4];
#pragma unroll
    for (int i = 0; i < 8; i++)
#pragma unroll
        for (int j = 0; j < 4; j++) acc[i][j] = 0.f;

    for (int kt = 0; kt < CS; kt += 32){
#pragma unroll
        for (int u = 0; u < 4; u++){
            int t4 = tid + u*128;
            int row = t4 >> 3, kq = t4 & 7;
            int c = kt + kq*4;
            int h = c / HD;
            int gi = m0 + row;
            const float* p = g_opart + (size_t)gi*CS + c;
            float4 v = make_float4(0.f, 0.f, 0.f, 0.f);
#pragma unroll
            for (int s = 0; s < NSPLIT; s++){
                float ws = wsm[row][h][s];
                float4 vs = *(const float4*)(p + (size_t)s*OPS);
                v.x = fmaf(ws, vs.x, v.x); v.y = fmaf(ws, vs.y, v.y);
                v.z = fmaf(ws, vs.z, v.z); v.w = fmaf(ws, vs.w, v.w);
            }
            As[(kq*4+0)*68+row] = v.x; As[(kq*4+1)*68+row] = v.y;
            As[(kq*4+2)*68+row] = v.z; As[(kq*4+3)*68+row] = v.w;
        }
#pragma unroll
        for (int u = 0; u < 4; u++){
            int t4 = tid + u*128;
            int row = t4 >> 3, kq = t4 & 7;
            float4 v = *(const float4*)(Wo + (size_t)(n0 + row)*CS + kt + kq*4);
            Bs[(kq*4+0)*68+row] = v.x; Bs[(kq*4+1)*68+row] = v.y;
            Bs[(kq*4+2)*68+row] = v.z; Bs[(kq*4+3)*68+row] = v.w;
        }
        __syncthreads();
#pragma unroll
        for (int kk = 0; kk < 32; kk++){
            float af[8], bf[4];
            *(float4*)&af[0] = *(const float4*)&As[kk*68 + ty*8];
            *(float4*)&af[4] = *(const float4*)&As[kk*68 + ty*8 + 4];
            *(float4*)&bf[0] = *(const float4*)&Bs[kk*68 + tx*4];
#pragma unroll
            for (int i = 0; i < 8; i++)
#pragma unroll
                for (int j = 0; j < 4; j++)
                    acc[i][j] = fmaf(af[i], bf[j], acc[i][j]);
        }
        __syncthreads();
    }

#pragma unroll
    for (int i = 0; i < 8; i++){
        int row = m0 + ty*8 + i;
#pragma unroll
        for (int j = 0; j < 4; j++){
            int col = n0 + tx*4 + j;
            float y  = acc[i][j] + bo[col];
            float gp = g_gate[(size_t)row*CS + col] + bg[col];
            float gg = 1.f / (1.f + __expf(-gp));
            out[(size_t)row*CS + col] = single[(size_t)row*CS + col] + gg * y;
        }
    }
}

// -------------------- launch --------------------
extern "C" void kernel_launch(void* const* d_in, const int* in_sizes, int n_in,
                              void* d_out, int out_size){
    const float* single = (const float*)d_in[0];
    const float* pair   = (const float*)d_in[1];
    const float* gs     = (const float*)d_in[2];
    const float* bs     = (const float*)d_in[3];
    const float* gz     = (const float*)d_in[4];
    const float* bz     = (const float*)d_in[5];
    const float* Wq     = (const float*)d_in[6];
    const float* Wk     = (const float*)d_in[7];
    const float* Wv     = (const float*)d_in[8];
    const float* Wb     = (const float*)d_in[9];
    const float* Wo     = (const float*)d_in[10];
    const float* bo     = (const float*)d_in[11];
    const float* Wg     = (const float*)d_in[12];
    const float* bg     = (const float*)d_in[13];
    float* out = (float*)d_out;

    // ln_pair_bias kept in 4th slot (profiler captures launch #4).
    conv_w_kernel<<<576, 256>>>(Wq, Wk, Wv, Wg);
    ln_single_kernel<<<L, 128>>>(single, gs, bs);
    qkvg_mma<<<dim3(1536/64, L/64), 256>>>();
    ln_pair_bias_kernel<<<dim3(6, L), 128>>>((const float4*)pair, gz, bz, Wb);
    attn_fused<<<dim3(NSPLIT, L/64, NH), 128>>>();
    final_kernel<<<dim3(CS/64, L/64), 128>>>(Wo, bo, single, bg, out);
}

// round 16
// speedup vs baseline: 1.1406x; 1.0002x over previous
#include <cuda_runtime.h>
#include <cuda_bf16.h>
#include <cstdint>
#include <math.h>

// AttentionWithPairBias: B=1, L=768, C_S=384, C_Z=128, H=8, HD=48
#define L 768
#define CS 384
#define NH 8
#define HD 48
#define LL (L*L)
#define OPS (L*CS)
#define NSPLIT 4

// -------------------- scratch (device globals; no allocs) --------------------
__device__ float g_bias[(size_t)NH*LL];  // pair bias (fp32), read by attn
__device__ float g_gate[L*CS];
__device__ float g_opart[NSPLIT*OPS];    // unnormalized O per j-split
__device__ float2 g_stat[NSPLIT*NH*L];   // per split: (m, l) per (h, i)
__device__ __nv_bfloat16 g_ah[L*CS], g_al[L*CS];         // layernorm(single) hi/lo
__device__ __nv_bfloat16 g_wh[4*CS*CS], g_wl[4*CS*CS];   // Wq|Wk|Wv|Wg rows, hi/lo
__device__ __nv_bfloat16 g_qh[L*CS], g_ql[L*CS];         // Q hi/lo
__device__ __nv_bfloat16 g_kh[L*CS], g_kl[L*CS];         // K hi/lo
__device__ __nv_bfloat16 g_vth[CS*L], g_vtl[CS*L];       // V^T hi/lo: [d][j]

// -------------------- warp helpers --------------------
__device__ __forceinline__ float warp_sum(float v){
#pragma unroll
    for (int o = 16; o; o >>= 1) v += __shfl_xor_sync(0xffffffffu, v, o);
    return v;
}

// -------------------- mma.sync / ldmatrix / cp.async (plain PTX, sm_80+) ----
__device__ __forceinline__ uint32_t smem_u32(const void* p){
    uint32_t a;
    asm("{ .reg .u64 t; cvta.to.shared.u64 t, %1; cvt.u32.u64 %0, t; }" : "=r"(a) : "l"(p));
    return a;
}
__device__ __forceinline__ void ldsm4(uint32_t* r, uint32_t addr){
    asm volatile("ldmatrix.sync.aligned.m8n8.x4.shared.b16 {%0,%1,%2,%3}, [%4];"
        : "=r"(r[0]), "=r"(r[1]), "=r"(r[2]), "=r"(r[3]) : "r"(addr));
}
__device__ __forceinline__ void mma16816(float* c, const uint32_t* a, const uint32_t* b){
    asm volatile(
        "mma.sync.aligned.m16n8k16.row.col.f32.bf16.bf16.f32 "
        "{%0,%1,%2,%3}, {%4,%5,%6,%7}, {%8,%9}, {%0,%1,%2,%3};"
        : "+f"(c[0]), "+f"(c[1]), "+f"(c[2]), "+f"(c[3])
        : "r"(a[0]), "r"(a[1]), "r"(a[2]), "r"(a[3]), "r"(b[0]), "r"(b[1]));
}
__device__ __forceinline__ void cpa16(uint32_t dst, const void* src){
    asm volatile("cp.async.cg.shared.global [%0], [%1], 16;" :: "r"(dst), "l"(src));
}
#define CPA_COMMIT() asm volatile("cp.async.commit_group;" ::: "memory")
#define CPA_WAIT1()  asm volatile("cp.async.wait_group 1;" ::: "memory")
#define CPA_WAIT0()  asm volatile("cp.async.wait_group 0;" ::: "memory")

// slab: rows x 16 bf16 payload (32B), pitch 48B (conflict-free ldmatrix)
__device__ __forceinline__ void ldA(uint32_t a[4], uint32_t slab, int wm, int t){
    ldsm4(a, slab + (uint32_t)((wm + (t & 15))*48 + (t >> 4)*16));
}
__device__ __forceinline__ void ldB(uint32_t b[4], uint32_t slab, int nb16, int t){
    ldsm4(b, slab + (uint32_t)((nb16 + ((t >> 4) << 3) + (t & 7))*48 + ((t >> 3) & 1)*16));
}
__device__ __forceinline__ uint32_t packbf2(float a, float b){
    __nv_bfloat162 t = __halves2bfloat162(__float2bfloat16(a), __float2bfloat16(b));
    return *(uint32_t*)&t;
}

// -------------------- K0: split Wq|Wk|Wv|Wg into bf16 hi/lo ------------------
__global__ void conv_w_kernel(const float* __restrict__ Wq, const float* __restrict__ Wk,
                              const float* __restrict__ Wv, const float* __restrict__ Wg){
    int idx = blockIdx.x*256 + threadIdx.x;
    int n  = idx / 96;
    int kq = idx - n*96;
    int which = n / 384;
    int r = n - which*384;
    const float* W = (which == 0) ? Wq : (which == 1) ? Wk : (which == 2) ? Wv : Wg;
    float4 v = *(const float4*)(W + (size_t)r*CS + kq*4);
    float x[4] = {v.x, v.y, v.z, v.w};
    __nv_bfloat16 h[4], l[4];
#pragma unroll
    for (int e = 0; e < 4; e++){
        h[e] = __float2bfloat16(x[e]);
        l[e] = __float2bfloat16(x[e] - __bfloat162float(h[e]));
    }
    size_t o = (size_t)n*CS + kq*4;
    *(__nv_bfloat162*)(g_wh + o)     = __halves2bfloat162(h[0], h[1]);
    *(__nv_bfloat162*)(g_wh + o + 2) = __halves2bfloat162(h[2], h[3]);
    *(__nv_bfloat162*)(g_wl + o)     = __halves2bfloat162(l[0], l[1]);
    *(__nv_bfloat162*)(g_wl + o + 2) = __halves2bfloat162(l[2], l[3]);
}

// -------------------- K1: layernorm(single) -> bf16 hi/lo --------------------
__global__ void ln_single_kernel(const float* __restrict__ x,
                                 const float* __restrict__ g,
                                 const float* __restrict__ b){
    __shared__ float rs[4], rq[4];
    int i = blockIdx.x, t = threadIdx.x;     // 128 threads
    int lane = t & 31, w = t >> 5;
    float v[3];
#pragma unroll
    for (int e = 0; e < 3; e++) v[e] = x[i*CS + e*128 + t];
    float s = v[0] + v[1] + v[2];
    float q = v[0]*v[0] + v[1]*v[1] + v[2]*v[2];
    s = warp_sum(s); q = warp_sum(q);
    if (lane == 0){ rs[w] = s; rq[w] = q; }
    __syncthreads();
    s = rs[0] + rs[1] + rs[2] + rs[3];
    q = rq[0] + rq[1] + rq[2] + rq[3];
    float mu   = s * (1.f/CS);
    float var  = q * (1.f/CS) - mu*mu;
    float rstd = rsqrtf(var + 1e-5f);
#pragma unroll
    for (int e = 0; e < 3; e++){
        int c = e*128 + t;
        float y = (v[e] - mu) * rstd * g[c] + b[c];
        __nv_bfloat16 hh = __float2bfloat16(y);
        g_ah[i*CS + c] = hh;
        g_al[i*CS + c] = __float2bfloat16(y - __bfloat162float(hh));
    }
}

// -------------------- K2: layernorm(pair) + bias = zn @ Wb -------------------
// v6: thread-per-j, cp.async.cg staging (no LDG->reg->STS round trip), XOR-
// swizzled pitch-32 rows so compute reads are conflict-free LDS.128.
// 128 j per block, 4 chunks of 32 channels, 2-deep pipeline.
__global__ void __launch_bounds__(128) ln_pair_bias_kernel(
                                    const float4* __restrict__ z4,
                                    const float* __restrict__ gz,
                                    const float* __restrict__ bz,
                                    const float* __restrict__ Wb){
    __shared__ __align__(16) float zs[2*128*32];  // 2 bufs x 128 rows x 128B
    __shared__ float gzw[128*8];
    __shared__ float GB[16];
    const uint32_t sbz = smem_u32(zs);
    const int tid = threadIdx.x;
    const int i   = blockIdx.y;
    const int jt0 = blockIdx.x * 128;

    for (int p = tid; p < 1024; p += 128){
        int c = p >> 3, h = p & 7;
        gzw[p] = gz[c] * Wb[c*8 + h];
    }
    __syncthreads();
    if (tid < 8){
        float G = 0.f, B = 0.f;
        for (int c = 0; c < 128; c++){
            G += gzw[c*8 + tid];
            B = fmaf(bz[c], Wb[c*8 + tid], B);
        }
        GB[tid] = G; GB[8 + tid] = B;
    }

    const float4* zbase = z4 + ((size_t)i*L + jt0)*32;

    // async-load one 32-channel chunk into buffer buf (swizzled chunk slots)
    auto load = [&](int buf, int ch){
#pragma unroll
        for (int u = 0; u < 8; u++){
            int idx = tid + u*128;           // [0,1024): 128 rows x 8 float4
            int j = idx >> 3, cq = idx & 7;
            cpa16(sbz + (uint32_t)(buf*16384 + j*128 + ((cq ^ (j & 7))*16)),
                  zbase + (size_t)j*32 + ch*8 + cq);
        }
        CPA_COMMIT();
    };

    load(0, 0);
    float s = 0.f, q = 0.f;
    float d[8] = {0,0,0,0,0,0,0,0};

#pragma unroll
    for (int ch = 0; ch < 4; ch++){
        if (ch + 1 < 4){ load((ch+1) & 1, ch+1); CPA_WAIT1(); }
        else CPA_WAIT0();
        __syncthreads();
        const float* zrow = zs + (ch & 1)*4096 + tid*32;
        const int sw = tid & 7;
        const float* gw = gzw + ch*32*8;
#pragma unroll
        for (int c4 = 0; c4 < 8; c4++){
            float4 zv = *(const float4*)(zrow + ((c4 ^ sw) << 2));
            // note: slot (c4^sw) holds channels ((c4^sw)^sw)*4 = c4*4 ✓
            float z0 = zv.x, z1 = zv.y, z2 = zv.z, z3 = zv.w;
            s += z0 + z1 + z2 + z3;
            q = fmaf(z0,z0, fmaf(z1,z1, fmaf(z2,z2, fmaf(z3,z3, q))));
            const float* g0 = gw + c4*32;     // 4 channels x 8 heads
#pragma unroll
            for (int e = 0; e < 4; e++){
                float z = (e==0)?z0:(e==1)?z1:(e==2)?z2:z3;
                float4 w0 = *(const float4*)(g0 + e*8);
                float4 w1 = *(const float4*)(g0 + e*8 + 4);
                d[0] = fmaf(z, w0.x, d[0]);
                d[1] = fmaf(z, w0.y, d[1]);
                d[2] = fmaf(z, w0.z, d[2]);
                d[3] = fmaf(z, w0.w, d[3]);
                d[4] = fmaf(z, w1.x, d[4]);
                d[5] = fmaf(z, w1.y, d[5]);
                d[6] = fmaf(z, w1.z, d[6]);
                d[7] = fmaf(z, w1.w, d[7]);
            }
        }
        __syncthreads();
    }

    float mu   = s * (1.f/128.f);
    float var  = q * (1.f/128.f) - mu*mu;
    float rstd = rsqrtf(var + 1e-5f);
    float nm   = -rstd * mu;
    size_t jg  = (size_t)i*L + jt0 + tid;
#pragma unroll
    for (int h = 0; h < 8; h++)
        g_bias[(size_t)h*LL + jg] = fmaf(rstd, d[h], fmaf(nm, GB[h], GB[8+h]));
}

// -------------------- K3: Q,K,V^T,Gate (pipelined mma) -----------------------
#define QCH 12288
__global__ void __launch_bounds__(256) qkvg_mma(){
    __shared__ __align__(16) char sm[2*QCH];
    const uint32_t sb = smem_u32(sm);
    const int tid = threadIdx.x, lane = tid & 31, wid = tid >> 5;
    const int wm16 = (wid & 3) * 16, wn32 = (wid >> 2) * 32;
    const int m0 = blockIdx.y * 64;
    const int ng = blockIdx.x * 64;

    float acc[4][4];
#pragma unroll
    for (int b = 0; b < 4; b++)
#pragma unroll
        for (int c = 0; c < 4; c++) acc[b][c] = 0.f;

    auto load = [&](int buf, int ch){
        int k = ch * 16;
#pragma unroll
        for (int u = 0; u < 2; u++){
            int idx = tid + u*256;
            int s = idx >> 7, rc = idx & 127, r = rc >> 1, c = rc & 1;
            const __nv_bfloat16* src =
                (s == 0) ? g_ah + (size_t)(m0+r)*CS + k + c*8 :
                (s == 1) ? g_al + (size_t)(m0+r)*CS + k + c*8 :
                (s == 2) ? g_wh + (size_t)(ng+r)*CS + k + c*8 :
                           g_wl + (size_t)(ng+r)*CS + k + c*8;
            cpa16(sb + buf*QCH + s*3072 + r*48 + c*16, src);
        }
        CPA_COMMIT();
    };

    load(0, 0);
    for (int ch = 0; ch < 24; ch++){
        if (ch + 1 < 24){ load((ch+1) & 1, ch+1); CPA_WAIT1(); }
        else CPA_WAIT0();
        __syncthreads();
        uint32_t base = sb + (ch & 1)*QCH;
        uint32_t ah[4], al[4], bh[2][4], bl[2][4];
        ldA(ah, base,        wm16, lane);
        ldA(al, base + 3072, wm16, lane);
#pragma unroll
        for (int pr = 0; pr < 2; pr++){
            ldB(bh[pr], base + 6144, wn32 + pr*16, lane);
            ldB(bl[pr], base + 9216, wn32 + pr*16, lane);
        }
#pragma unroll
        for (int nt = 0; nt < 4; nt++){
            const uint32_t* bhp = &bh[nt>>1][(nt&1)*2];
            const uint32_t* blp = &bl[nt>>1][(nt&1)*2];
            mma16816(acc[nt], ah, bhp);
            mma16816(acc[nt], al, bhp);
            mma16816(acc[nt], ah, blp);
        }
        __syncthreads();
    }

    const int which = ng / 384;
    const int nloc  = ng - which*384;
    const int rb = m0 + wm16 + (lane >> 2);
    const int cb = wn32 + (lane & 3)*2;
    if (which <= 1){
        __nv_bfloat16* PH = which ? g_kh : g_qh;
        __nv_bfloat16* PL = which ? g_kl : g_ql;
#pragma unroll
        for (int half = 0; half < 2; half++){
            int i = rb + half*8;
#pragma unroll
            for (int nt = 0; nt < 4; nt++){
                int cg = nloc + cb + nt*8;
                float v0 = acc[nt][half*2], v1 = acc[nt][half*2+1];
                __nv_bfloat16 h0 = __float2bfloat16(v0);
                __nv_bfloat16 h1 = __float2bfloat16(v1);
                __nv_bfloat16 l0 = __float2bfloat16(v0 - __bfloat162float(h0));
                __nv_bfloat16 l1 = __float2bfloat16(v1 - __bfloat162float(h1));
                *(__nv_bfloat162*)(PH + (size_t)i*CS + cg) = __halves2bfloat162(h0, h1);
                *(__nv_bfloat162*)(PL + (size_t)i*CS + cg) = __halves2bfloat162(l0, l1);
            }
        }
    } else if (which == 2){
#pragma unroll
        for (int half = 0; half < 2; half++){
            int i = rb + half*8;
#pragma unroll
            for (int nt = 0; nt < 4; nt++){
                int cg = nloc + cb + nt*8;
                float v0 = acc[nt][half*2], v1 = acc[nt][half*2+1];
                __nv_bfloat16 h0 = __float2bfloat16(v0);
                __nv_bfloat16 h1 = __float2bfloat16(v1);
                g_vth[(size_t)cg*L + i]     = h0;
                g_vth[(size_t)(cg+1)*L + i] = h1;
                g_vtl[(size_t)cg*L + i]     = __float2bfloat16(v0 - __bfloat162float(h0));
                g_vtl[(size_t)(cg+1)*L + i] = __float2bfloat16(v1 - __bfloat162float(h1));
            }
        }
    } else {
#pragma unroll
        for (int half = 0; half < 2; half++){
            int i = rb + half*8;
#pragma unroll
            for (int nt = 0; nt < 4; nt++){
                int cg = nloc + cb + nt*8;
                float2 v = make_float2(acc[nt][half*2], acc[nt][half*2+1]);
                *(float2*)(g_gate + (size_t)i*CS + cg) = v;
            }
        }
    }
}

// -------------------- K4: fused flash attention ------------------------------
__global__ void __launch_bounds__(128) attn_fused(){
    __shared__ __align__(16) char sm[36864];
    const uint32_t sb = smem_u32(sm);
    const int tid = threadIdx.x, lane = tid & 31, wid = tid >> 5;
    const int js = blockIdx.x;
    const int m0 = blockIdx.y * 64;
    const int h  = blockIdx.z;
    const int jb = js * 192;
    const float sc = 0.14433756729740643f;

#pragma unroll
    for (int u = 0; u < 6; u++){
        int idx = tid + u*128;
        int plane = idx / 384, rem = idx - plane*384;
        int s = rem >> 7, rc = rem & 127, r = rc >> 1, c = rc & 1;
        const __nv_bfloat16* src = (plane ? g_ql : g_qh)
            + (size_t)(m0+r)*CS + h*HD + s*16 + c*8;
        *(uint4*)(sm + plane*9216 + s*3072 + r*48 + c*16) = *(const uint4*)src;
    }
    __syncthreads();
    uint32_t qh[3][4], ql[3][4];
#pragma unroll
    for (int s = 0; s < 3; s++){
        ldA(qh[s], sb +        (uint32_t)(s*3072), wid*16, lane);
        ldA(ql[s], sb + 9216 + (uint32_t)(s*3072), wid*16, lane);
    }

    float mrow[2] = {-INFINITY, -INFINITY};
    float lrow[2] = {0.f, 0.f};
    float o[6][4];
#pragma unroll
    for (int dn = 0; dn < 6; dn++)
#pragma unroll
        for (int e = 0; e < 4; e++) o[dn][e] = 0.f;

    const int r0 = lane >> 2;
    const int c0 = (lane & 3) * 2;

    for (int step = 0; step < 3; step++){
        int j0 = jb + step*64;
        __syncthreads();
#pragma unroll
        for (int u = 0; u < 12; u++){
            int idx = tid + u*128;
            if (idx < 768){
                int plane = idx / 384, rem = idx - plane*384;
                int s = rem >> 7, rc = rem & 127, r = rc >> 1, c = rc & 1;
                const __nv_bfloat16* src = (plane ? g_kl : g_kh)
                    + (size_t)(j0+r)*CS + h*HD + s*16 + c*8;
                *(uint4*)(sm + plane*9216 + s*3072 + r*48 + c*16) = *(const uint4*)src;
            } else {
                int q2 = idx - 768;
                int plane = q2 / 384, rem = q2 - plane*384;
                int g = rem / 96, rc = rem - g*96, r = rc >> 1, c = rc & 1;
                const __nv_bfloat16* src = (plane ? g_vtl : g_vth)
                    + (size_t)(h*HD + r)*L + j0 + g*16 + c*8;
                *(uint4*)(sm + 18432 + plane*9216 + g*2304 + r*48 + c*16) = *(const uint4*)src;
            }
        }
        __syncthreads();

        float s_[8][4];
#pragma unroll
        for (int nt = 0; nt < 8; nt++)
#pragma unroll
            for (int e = 0; e < 4; e++) s_[nt][e] = 0.f;
#pragma unroll
        for (int sl = 0; sl < 3; sl++){
            uint32_t bh[4][4], bl[4][4];
#pragma unroll
            for (int p = 0; p < 4; p++){
                ldB(bh[p], sb +        (uint32_t)(sl*3072), p*16, lane);
                ldB(bl[p], sb + 9216 + (uint32_t)(sl*3072), p*16, lane);
            }
#pragma unroll
            for (int nt = 0; nt < 8; nt++){
                const uint32_t* bhp = &bh[nt>>1][(nt&1)*2];
                const uint32_t* blp = &bl[nt>>1][(nt&1)*2];
                mma16816(s_[nt], qh[sl], bhp);
                mma16816(s_[nt], ql[sl], bhp);
                mma16816(s_[nt], qh[sl], blp);
            }
        }

#pragma unroll
        for (int nt = 0; nt < 8; nt++)
#pragma unroll
            for (int e = 0; e < 2; e++){
                int i = m0 + wid*16 + r0 + e*8;
                float2 b = *(const float2*)(g_bias + (size_t)h*LL + (size_t)i*L
                                            + j0 + nt*8 + c0);
                s_[nt][e*2]   = fmaf(s_[nt][e*2],   sc, b.x);
                s_[nt][e*2+1] = fmaf(s_[nt][e*2+1], sc, b.y);
            }

#pragma unroll
        for (int e = 0; e < 2; e++){
            float mx = -INFINITY;
#pragma unroll
            for (int nt = 0; nt < 8; nt++)
                mx = fmaxf(mx, fmaxf(s_[nt][e*2], s_[nt][e*2+1]));
            mx = fmaxf(mx, __shfl_xor_sync(0xffffffffu, mx, 1));
            mx = fmaxf(mx, __shfl_xor_sync(0xffffffffu, mx, 2));
            float mn = fmaxf(mrow[e], mx);
            float alpha = __expf(mrow[e] - mn);
            mrow[e] = mn;
            float sum = 0.f;
#pragma unroll
            for (int nt = 0; nt < 8; nt++){
                float p0 = __expf(s_[nt][e*2]   - mn);
                float p1 = __expf(s_[nt][e*2+1] - mn);
                s_[nt][e*2] = p0; s_[nt][e*2+1] = p1;
                sum += p0 + p1;
            }
            sum += __shfl_xor_sync(0xffffffffu, sum, 1);
            sum += __shfl_xor_sync(0xffffffffu, sum, 2);
            lrow[e] = lrow[e]*alpha + sum;
#pragma unroll
            for (int dn = 0; dn < 6; dn++){
                o[dn][e*2]   *= alpha;
                o[dn][e*2+1] *= alpha;
            }
        }

#pragma unroll
        for (int g = 0; g < 4; g++){
            uint32_t aH[4], aL[4];
#pragma unroll
            for (int half = 0; half < 2; half++){
                int nt = 2*g + half;
#pragma unroll
                for (int e = 0; e < 2; e++){
                    float p0 = s_[nt][e*2], p1 = s_[nt][e*2+1];
                    uint32_t hi = packbf2(p0, p1);
                    __nv_bfloat162 hv = *(__nv_bfloat162*)&hi;
                    uint32_t lo = packbf2(p0 - __bfloat162float(hv.x),
                                          p1 - __bfloat162float(hv.y));
                    aH[half*2 + e] = hi;
                    aL[half*2 + e] = lo;
                }
            }
            uint32_t vh[3][4], vl[3][4];
#pragma unroll
            for (int q = 0; q < 3; q++){
                ldB(vh[q], sb + 18432 + (uint32_t)(g*2304), q*16, lane);
                ldB(vl[q], sb + 27648 + (uint32_t)(g*2304), q*16, lane);
            }
#pragma unroll
            for (int dn = 0; dn < 6; dn++){
                const uint32_t* vhp = &vh[dn>>1][(dn&1)*2];
                const uint32_t* vlp = &vl[dn>>1][(dn&1)*2];
                mma16816(o[dn], aH, vhp);
                mma16816(o[dn], aL, vhp);
                mma16816(o[dn], aH, vlp);
            }
        }
    }

#pragma unroll
    for (int e = 0; e < 2; e++){
        int i = m0 + wid*16 + r0 + e*8;
        float* op = g_opart + (size_t)js*OPS + (size_t)i*CS + h*HD;
#pragma unroll
        for (int dn = 0; dn < 6; dn++)
            *(float2*)(op + dn*8 + c0) = make_float2(o[dn][e*2], o[dn][e*2+1]);
        if ((lane & 3) == 0)
            g_stat[js*NH*L + h*L + i] = make_float2(mrow[e], lrow[e]);
    }
}

// -------------------- K5: out = single + sigmoid(gate+bg)*(O@Wo^T+bo) -------
__global__ void __launch_bounds__(128) final_kernel(
        const float* __restrict__ Wo, const float* __restrict__ bo,
        const float* __restrict__ single, const float* __restrict__ bg,
        float* __restrict__ out){
    __shared__ float As[32*68];
    __shared__ float Bs[32*68];
    __shared__ float wsm[64][8][NSPLIT];
    const int tid = threadIdx.x;
    const int tx  = tid % 16, ty = tid / 16;
    const int m0 = blockIdx.y*64, n0 = blockIdx.x*64;

    for (int p = tid; p < 64*8; p += 128){
        int row = p >> 3, h = p & 7;
        int gi = m0 + row;
        float2 st[NSPLIT];
        float M = -INFINITY;
#pragma unroll
        for (int s = 0; s < NSPLIT; s++){
            st[s] = g_stat[s*NH*L + h*L + gi];
            M = fmaxf(M, st[s].x);
        }
        float w[NSPLIT], den = 0.f;
#pragma unroll
        for (int s = 0; s < NSPLIT; s++){
            w[s] = __expf(st[s].x - M);
            den = fmaf(w[s], st[s].y, den);
        }
        float inv = 1.f / den;
#pragma unroll
        for (int s = 0; s < NSPLIT; s++) wsm[row][h][s] = w[s]*inv;
    }
    __syncthreads();

    float acc[8][4];
#pragma unroll
    for (int i = 0; i < 8; i++)
#pragma unroll
        for (int j = 0; j < 4; j++) acc[i][j] = 0.f;

    for (int kt = 0; kt < CS; kt += 32){
#pragma unroll
        for (int u = 0; u < 4; u++){
            int t4 = tid + u*128;
            int row = t4 >> 3, kq = t4 & 7;
            int c = kt + kq*4;
            int h = c / HD;
            int gi = m0 + row;
            const float* p = g_opart + (size_t)gi*CS + c;
            float4 v = make_float4(0.f, 0.f, 0.f, 0.f);
#pragma unroll
            for (int s = 0; s < NSPLIT; s++){
                float ws = wsm[row][h][s];
                float4 vs = *(const float4*)(p + (size_t)s*OPS);
                v.x = fmaf(ws, vs.x, v.x); v.y = fmaf(ws, vs.y, v.y);
                v.z = fmaf(ws, vs.z, v.z); v.w = fmaf(ws, vs.w, v.w);
            }
            As[(kq*4+0)*68+row] = v.x; As[(kq*4+1)*68+row] = v.y;
            As[(kq*4+2)*68+row] = v.z; As[(kq*4+3)*68+row] = v.w;
        }
#pragma unroll
        for (int u = 0; u < 4; u++){
            int t4 = tid + u*128;
            int row = t4 >> 3, kq = t4 & 7;
            float4 v = *(const float4*)(Wo + (size_t)(n0 + row)*CS + kt + kq*4);
            Bs[(kq*4+0)*68+row] = v.x; Bs[(kq*4+1)*68+row] = v.y;
            Bs[(kq*4+2)*68+row] = v.z; Bs[(kq*4+3)*68+row] = v.w;
        }
        __syncthreads();
#pragma unroll
        for (int kk = 0; kk < 32; kk++){
            float af[8], bf[4];
            *(float4*)&af[0] = *(const float4*)&As[kk*68 + ty*8];
            *(float4*)&af[4] = *(const float4*)&As[kk*68 + ty*8 + 4];
            *(float4*)&bf[0] = *(const float4*)&Bs[kk*68 + tx*4];
#pragma unroll
            for (int i = 0; i < 8; i++)
#pragma unroll
                for (int j = 0; j < 4; j++)
                    acc[i][j] = fmaf(af[i], bf[j], acc[i][j]);
        }
        __syncthreads();
    }

#pragma unroll
    for (int i = 0; i < 8; i++){
        int row = m0 + ty*8 + i;
#pragma unroll
        for (int j = 0; j < 4; j++){
            int col = n0 + tx*4 + j;
            float y  = acc[i][j] + bo[col];
            float gp = g_gate[(size_t)row*CS + col] + bg[col];
            float gg = 1.f / (1.f + __expf(-gp));
            out[(size_t)row*CS + col] = single[(size_t)row*CS + col] + gg * y;
        }
    }
}

// -------------------- launch --------------------
extern "C" void kernel_launch(void* const* d_in, const int* in_sizes, int n_in,
                              void* d_out, int out_size){
    const float* single = (const float*)d_in[0];
    const float* pair   = (const float*)d_in[1];
    const float* gs     = (const float*)d_in[2];
    const float* bs     = (const float*)d_in[3];
    const float* gz     = (const float*)d_in[4];
    const float* bz     = (const float*)d_in[5];
    const float* Wq     = (const float*)d_in[6];
    const float* Wk     = (const float*)d_in[7];
    const float* Wv     = (const float*)d_in[8];
    const float* Wb     = (const float*)d_in[9];
    const float* Wo     = (const float*)d_in[10];
    const float* bo     = (const float*)d_in[11];
    const float* Wg     = (const float*)d_in[12];
    const float* bg     = (const float*)d_in[13];
    float* out = (float*)d_out;

    // ln_pair_bias kept in 4th slot (profiler captures launch #4).
    conv_w_kernel<<<576, 256>>>(Wq, Wk, Wv, Wg);
    ln_single_kernel<<<L, 128>>>(single, gs, bs);
    qkvg_mma<<<dim3(1536/64, L/64), 256>>>();
    ln_pair_bias_kernel<<<dim3(6, L), 128>>>((const float4*)pair, gz, bz, Wb);
    attn_fused<<<dim3(NSPLIT, L/64, NH), 128>>>();
    final_kernel<<<dim3(CS/64, L/64), 128>>>(Wo, bo, single, bg, out);
}

// round 17
// speedup vs baseline: 1.1659x; 1.0222x over previous
#include <cuda_runtime.h>
#include <cuda_bf16.h>
#include <cstdint>
#include <math.h>

// AttentionWithPairBias: B=1, L=768, C_S=384, C_Z=128, H=8, HD=48
#define L 768
#define CS 384
#define NH 8
#define HD 48
#define LL (L*L)
#define OPS (L*CS)
#define NSPLIT 4

// -------------------- scratch (device globals; no allocs) --------------------
__device__ float g_bias[(size_t)NH*LL];  // pair bias (fp32), read by attn
__device__ float g_gate[L*CS];
__device__ float g_opart[NSPLIT*OPS];    // unnormalized O per j-split
__device__ float2 g_stat[NSPLIT*NH*L];   // per split: (m, l) per (h, i)
__device__ __nv_bfloat16 g_ah[L*CS], g_al[L*CS];         // layernorm(single) hi/lo
__device__ __nv_bfloat16 g_wh[4*CS*CS], g_wl[4*CS*CS];   // Wq|Wk|Wv|Wg rows, hi/lo
__device__ __nv_bfloat16 g_qh[L*CS], g_ql[L*CS];         // Q hi/lo
__device__ __nv_bfloat16 g_kh[L*CS], g_kl[L*CS];         // K hi/lo
__device__ __nv_bfloat16 g_vth[CS*L], g_vtl[CS*L];       // V^T hi/lo: [d][j]

// -------------------- warp helpers --------------------
__device__ __forceinline__ float warp_sum(float v){
#pragma unroll
    for (int o = 16; o; o >>= 1) v += __shfl_xor_sync(0xffffffffu, v, o);
    return v;
}

// -------------------- mma.sync / ldmatrix / cp.async (plain PTX, sm_80+) ----
__device__ __forceinline__ uint32_t smem_u32(const void* p){
    uint32_t a;
    asm("{ .reg .u64 t; cvta.to.shared.u64 t, %1; cvt.u32.u64 %0, t; }" : "=r"(a) : "l"(p));
    return a;
}
__device__ __forceinline__ void ldsm4(uint32_t* r, uint32_t addr){
    asm volatile("ldmatrix.sync.aligned.m8n8.x4.shared.b16 {%0,%1,%2,%3}, [%4];"
        : "=r"(r[0]), "=r"(r[1]), "=r"(r[2]), "=r"(r[3]) : "r"(addr));
}
__device__ __forceinline__ void mma16816(float* c, const uint32_t* a, const uint32_t* b){
    asm volatile(
        "mma.sync.aligned.m16n8k16.row.col.f32.bf16.bf16.f32 "
        "{%0,%1,%2,%3}, {%4,%5,%6,%7}, {%8,%9}, {%0,%1,%2,%3};"
        : "+f"(c[0]), "+f"(c[1]), "+f"(c[2]), "+f"(c[3])
        : "r"(a[0]), "r"(a[1]), "r"(a[2]), "r"(a[3]), "r"(b[0]), "r"(b[1]));
}
__device__ __forceinline__ void cpa16(uint32_t dst, const void* src){
    asm volatile("cp.async.cg.shared.global [%0], [%1], 16;" :: "r"(dst), "l"(src));
}
#define CPA_COMMIT() asm volatile("cp.async.commit_group;" ::: "memory")
#define CPA_WAIT1()  asm volatile("cp.async.wait_group 1;" ::: "memory")
#define CPA_WAIT0()  asm volatile("cp.async.wait_group 0;" ::: "memory")

// slab: rows x 16 bf16 payload (32B), pitch 48B (conflict-free ldmatrix)
__device__ __forceinline__ void ldA(uint32_t a[4], uint32_t slab, int wm, int t){
    ldsm4(a, slab + (uint32_t)((wm + (t & 15))*48 + (t >> 4)*16));
}
__device__ __forceinline__ void ldB(uint32_t b[4], uint32_t slab, int nb16, int t){
    ldsm4(b, slab + (uint32_t)((nb16 + ((t >> 4) << 3) + (t & 7))*48 + ((t >> 3) & 1)*16));
}
__device__ __forceinline__ uint32_t packbf2(float a, float b){
    __nv_bfloat162 t = __halves2bfloat162(__float2bfloat16(a), __float2bfloat16(b));
    return *(uint32_t*)&t;
}

// -------------------- K0: prep = conv_w (blocks 0..1151) + ln_single (rest) --
__global__ void __launch_bounds__(128) prep_kernel(
        const float* __restrict__ Wq, const float* __restrict__ Wk,
        const float* __restrict__ Wv, const float* __restrict__ Wg,
        const float* __restrict__ x,  const float* __restrict__ g,
        const float* __restrict__ b){
    if ((int)blockIdx.x < 1152){
        // ---- split Wq|Wk|Wv|Wg into bf16 hi/lo ----
        int idx = blockIdx.x*128 + threadIdx.x;   // 147456 float4 slots
        int n  = idx / 96;
        int kq = idx - n*96;
        int which = n / 384;
        int r = n - which*384;
        const float* W = (which == 0) ? Wq : (which == 1) ? Wk : (which == 2) ? Wv : Wg;
        float4 v = *(const float4*)(W + (size_t)r*CS + kq*4);
        float xx[4] = {v.x, v.y, v.z, v.w};
        __nv_bfloat16 h[4], l[4];
#pragma unroll
        for (int e = 0; e < 4; e++){
            h[e] = __float2bfloat16(xx[e]);
            l[e] = __float2bfloat16(xx[e] - __bfloat162float(h[e]));
        }
        size_t o = (size_t)n*CS + kq*4;
        *(__nv_bfloat162*)(g_wh + o)     = __halves2bfloat162(h[0], h[1]);
        *(__nv_bfloat162*)(g_wh + o + 2) = __halves2bfloat162(h[2], h[3]);
        *(__nv_bfloat162*)(g_wl + o)     = __halves2bfloat162(l[0], l[1]);
        *(__nv_bfloat162*)(g_wl + o + 2) = __halves2bfloat162(l[2], l[3]);
    } else {
        // ---- layernorm(single) -> bf16 hi/lo ----
        __shared__ float rs[4], rq[4];
        int i = blockIdx.x - 1152, t = threadIdx.x;   // 128 threads
        int lane = t & 31, w = t >> 5;
        float v[3];
#pragma unroll
        for (int e = 0; e < 3; e++) v[e] = x[i*CS + e*128 + t];
        float s = v[0] + v[1] + v[2];
        float q = v[0]*v[0] + v[1]*v[1] + v[2]*v[2];
        s = warp_sum(s); q = warp_sum(q);
        if (lane == 0){ rs[w] = s; rq[w] = q; }
        __syncthreads();
        s = rs[0] + rs[1] + rs[2] + rs[3];
        q = rq[0] + rq[1] + rq[2] + rq[3];
        float mu   = s * (1.f/CS);
        float var  = q * (1.f/CS) - mu*mu;
        float rstd = rsqrtf(var + 1e-5f);
#pragma unroll
        for (int e = 0; e < 3; e++){
            int c = e*128 + t;
            float y = (v[e] - mu) * rstd * g[c] + b[c];
            __nv_bfloat16 hh = __float2bfloat16(y);
            g_ah[i*CS + c] = hh;
            g_al[i*CS + c] = __float2bfloat16(y - __bfloat162float(hh));
        }
    }
}

// -------------------- K2: layernorm(pair) + bias = zn @ Wb -------------------
// v7: cp.async staging, 16-channel chunks (8 chunks, 2-deep pipeline),
// __launch_bounds__(128,8) for 50% occupancy. XOR slot swizzle keeps the
// compute-side LDS.128 conflict-free (8-lane phases cover all 32 banks).
__global__ void __launch_bounds__(128, 8) ln_pair_bias_kernel(
                                    const float4* __restrict__ z4,
                                    const float* __restrict__ gz,
                                    const float* __restrict__ bz,
                                    const float* __restrict__ Wb){
    __shared__ __align__(16) float zs[2*128*16];  // 2 bufs x 128 rows x 64B
    __shared__ float gzw[128*8];
    __shared__ float GB[16];
    const uint32_t sbz = smem_u32(zs);
    const int tid = threadIdx.x;
    const int i   = blockIdx.y;
    const int jt0 = blockIdx.x * 128;

    for (int p = tid; p < 1024; p += 128){
        int c = p >> 3, h = p & 7;
        gzw[p] = gz[c] * Wb[c*8 + h];
    }
    __syncthreads();
    if (tid < 8){
        float G = 0.f, B = 0.f;
        for (int c = 0; c < 128; c++){
            G += gzw[c*8 + tid];
            B = fmaf(bz[c], Wb[c*8 + tid], B);
        }
        GB[tid] = G; GB[8 + tid] = B;
    }

    const float4* zbase = z4 + ((size_t)i*L + jt0)*32;

    // async-load one 16-channel chunk; store slot cq at (cq ^ ((j>>1)&3))
    auto load = [&](int buf, int ch){
#pragma unroll
        for (int u = 0; u < 4; u++){
            int idx = tid + u*128;           // [0,512): 128 rows x 4 float4
            int j = idx >> 2, cq = idx & 3;
            cpa16(sbz + (uint32_t)(buf*8192 + j*64 + ((cq ^ ((j >> 1) & 3))*16)),
                  zbase + (size_t)j*32 + ch*4 + cq);
        }
        CPA_COMMIT();
    };

    load(0, 0);
    float s = 0.f, q = 0.f;
    float d[8] = {0,0,0,0,0,0,0,0};

#pragma unroll
    for (int ch = 0; ch < 8; ch++){
        if (ch + 1 < 8){ load((ch+1) & 1, ch+1); CPA_WAIT1(); }
        else CPA_WAIT0();
        __syncthreads();
        const float* zrow = zs + (ch & 1)*2048 + tid*16;
        const int sw = (tid >> 1) & 3;
        const float* gw = gzw + ch*16*8;
#pragma unroll
        for (int c4 = 0; c4 < 4; c4++){
            // slot (c4^sw) holds channel-group ((c4^sw)^sw) = c4
            float4 zv = *(const float4*)(zrow + ((c4 ^ sw) << 2));
            float z0 = zv.x, z1 = zv.y, z2 = zv.z, z3 = zv.w;
            s += z0 + z1 + z2 + z3;
            q = fmaf(z0,z0, fmaf(z1,z1, fmaf(z2,z2, fmaf(z3,z3, q))));
            const float* g0 = gw + c4*32;     // 4 channels x 8 heads
#pragma unroll
            for (int e = 0; e < 4; e++){
                float z = (e==0)?z0:(e==1)?z1:(e==2)?z2:z3;
                float4 w0 = *(const float4*)(g0 + e*8);
                float4 w1 = *(const float4*)(g0 + e*8 + 4);
                d[0] = fmaf(z, w0.x, d[0]);
                d[1] = fmaf(z, w0.y, d[1]);
                d[2] = fmaf(z, w0.z, d[2]);
                d[3] = fmaf(z, w0.w, d[3]);
                d[4] = fmaf(z, w1.x, d[4]);
                d[5] = fmaf(z, w1.y, d[5]);
                d[6] = fmaf(z, w1.z, d[6]);
                d[7] = fmaf(z, w1.w, d[7]);
            }
        }
        __syncthreads();
    }

    float mu   = s * (1.f/128.f);
    float var  = q * (1.f/128.f) - mu*mu;
    float rstd = rsqrtf(var + 1e-5f);
    float nm   = -rstd * mu;
    size_t jg  = (size_t)i*L + jt0 + tid;
#pragma unroll
    for (int h = 0; h < 8; h++)
        g_bias[(size_t)h*LL + jg] = fmaf(rstd, d[h], fmaf(nm, GB[h], GB[8+h]));
}

// -------------------- K3: Q,K,V^T,Gate (pipelined mma) -----------------------
#define QCH 12288
__global__ void __launch_bounds__(256) qkvg_mma(){
    __shared__ __align__(16) char sm[2*QCH];
    const uint32_t sb = smem_u32(sm);
    const int tid = threadIdx.x, lane = tid & 31, wid = tid >> 5;
    const int wm16 = (wid & 3) * 16, wn32 = (wid >> 2) * 32;
    const int m0 = blockIdx.y * 64;
    const int ng = blockIdx.x * 64;

    float acc[4][4];
#pragma unroll
    for (int b = 0; b < 4; b++)
#pragma unroll
        for (int c = 0; c < 4; c++) acc[b][c] = 0.f;

    auto load = [&](int buf, int ch){
        int k = ch * 16;
#pragma unroll
        for (int u = 0; u < 2; u++){
            int idx = tid + u*256;
            int s = idx >> 7, rc = idx & 127, r = rc >> 1, c = rc & 1;
            const __nv_bfloat16* src =
                (s == 0) ? g_ah + (size_t)(m0+r)*CS + k + c*8 :
                (s == 1) ? g_al + (size_t)(m0+r)*CS + k + c*8 :
                (s == 2) ? g_wh + (size_t)(ng+r)*CS + k + c*8 :
                           g_wl + (size_t)(ng+r)*CS + k + c*8;
            cpa16(sb + buf*QCH + s*3072 + r*48 + c*16, src);
        }
        CPA_COMMIT();
    };

    load(0, 0);
    for (int ch = 0; ch < 24; ch++){
        if (ch + 1 < 24){ load((ch+1) & 1, ch+1); CPA_WAIT1(); }
        else CPA_WAIT0();
        __syncthreads();
        uint32_t base = sb + (ch & 1)*QCH;
        uint32_t ah[4], al[4], bh[2][4], bl[2][4];
        ldA(ah, base,        wm16, lane);
        ldA(al, base + 3072, wm16, lane);
#pragma unroll
        for (int pr = 0; pr < 2; pr++){
            ldB(bh[pr], base + 6144, wn32 + pr*16, lane);
            ldB(bl[pr], base + 9216, wn32 + pr*16, lane);
        }
#pragma unroll
        for (int nt = 0; nt < 4; nt++){
            const uint32_t* bhp = &bh[nt>>1][(nt&1)*2];
            const uint32_t* blp = &bl[nt>>1][(nt&1)*2];
            mma16816(acc[nt], ah, bhp);
            mma16816(acc[nt], al, bhp);
            mma16816(acc[nt], ah, blp);
        }
        __syncthreads();
    }

    const int which = ng / 384;
    const int nloc  = ng - which*384;
    const int rb = m0 + wm16 + (lane >> 2);
    const int cb = wn32 + (lane & 3)*2;
    if (which <= 1){
        __nv_bfloat16* PH = which ? g_kh : g_qh;
        __nv_bfloat16* PL = which ? g_kl : g_ql;
#pragma unroll
        for (int half = 0; half < 2; half++){
            int i = rb + half*8;
#pragma unroll
            for (int nt = 0; nt < 4; nt++){
                int cg = nloc + cb + nt*8;
                float v0 = acc[nt][half*2], v1 = acc[nt][half*2+1];
                __nv_bfloat16 h0 = __float2bfloat16(v0);
                __nv_bfloat16 h1 = __float2bfloat16(v1);
                __nv_bfloat16 l0 = __float2bfloat16(v0 - __bfloat162float(h0));
                __nv_bfloat16 l1 = __float2bfloat16(v1 - __bfloat162float(h1));
                *(__nv_bfloat162*)(PH + (size_t)i*CS + cg) = __halves2bfloat162(h0, h1);
                *(__nv_bfloat162*)(PL + (size_t)i*CS + cg) = __halves2bfloat162(l0, l1);
            }
        }
    } else if (which == 2){
#pragma unroll
        for (int half = 0; half < 2; half++){
            int i = rb + half*8;
#pragma unroll
            for (int nt = 0; nt < 4; nt++){
                int cg = nloc + cb + nt*8;
                float v0 = acc[nt][half*2], v1 = acc[nt][half*2+1];
                __nv_bfloat16 h0 = __float2bfloat16(v0);
                __nv_bfloat16 h1 = __float2bfloat16(v1);
                g_vth[(size_t)cg*L + i]     = h0;
                g_vth[(size_t)(cg+1)*L + i] = h1;
                g_vtl[(size_t)cg*L + i]     = __float2bfloat16(v0 - __bfloat162float(h0));
                g_vtl[(size_t)(cg+1)*L + i] = __float2bfloat16(v1 - __bfloat162float(h1));
            }
        }
    } else {
#pragma unroll
        for (int half = 0; half < 2; half++){
            int i = rb + half*8;
#pragma unroll
            for (int nt = 0; nt < 4; nt++){
                int cg = nloc + cb + nt*8;
                float2 v = make_float2(acc[nt][half*2], acc[nt][half*2+1]);
                *(float2*)(g_gate + (size_t)i*CS + cg) = v;
            }
        }
    }
}

// -------------------- K4: fused flash attention ------------------------------
__global__ void __launch_bounds__(128) attn_fused(){
    __shared__ __align__(16) char sm[36864];
    const uint32_t sb = smem_u32(sm);
    const int tid = threadIdx.x, lane = tid & 31, wid = tid >> 5;
    const int js = blockIdx.x;
    const int m0 = blockIdx.y * 64;
    const int h  = blockIdx.z;
    const int jb = js * 192;
    const float sc = 0.14433756729740643f;

#pragma unroll
    for (int u = 0; u < 6; u++){
        int idx = tid + u*128;
        int plane = idx / 384, rem = idx - plane*384;
        int s = rem >> 7, rc = rem & 127, r = rc >> 1, c = rc & 1;
        const __nv_bfloat16* src = (plane ? g_ql : g_qh)
            + (size_t)(m0+r)*CS + h*HD + s*16 + c*8;
        *(uint4*)(sm + plane*9216 + s*3072 + r*48 + c*16) = *(const uint4*)src;
    }
    __syncthreads();
    uint32_t qh[3][4], ql[3][4];
#pragma unroll
    for (int s = 0; s < 3; s++){
        ldA(qh[s], sb +        (uint32_t)(s*3072), wid*16, lane);
        ldA(ql[s], sb + 9216 + (uint32_t)(s*3072), wid*16, lane);
    }

    float mrow[2] = {-INFINITY, -INFINITY};
    float lrow[2] = {0.f, 0.f};
    float o[6][4];
#pragma unroll
    for (int dn = 0; dn < 6; dn++)
#pragma unroll
        for (int e = 0; e < 4; e++) o[dn][e] = 0.f;

    const int r0 = lane >> 2;
    const int c0 = (lane & 3) * 2;

    for (int step = 0; step < 3; step++){
        int j0 = jb + step*64;
        __syncthreads();
#pragma unroll
        for (int u = 0; u < 12; u++){
            int idx = tid + u*128;
            if (idx < 768){
                int plane = idx / 384, rem = idx - plane*384;
                int s = rem >> 7, rc = rem & 127, r = rc >> 1, c = rc & 1;
                const __nv_bfloat16* src = (plane ? g_kl : g_kh)
                    + (size_t)(j0+r)*CS + h*HD + s*16 + c*8;
                *(uint4*)(sm + plane*9216 + s*3072 + r*48 + c*16) = *(const uint4*)src;
            } else {
                int q2 = idx - 768;
                int plane = q2 / 384, rem = q2 - plane*384;
                int g = rem / 96, rc = rem - g*96, r = rc >> 1, c = rc & 1;
                const __nv_bfloat16* src = (plane ? g_vtl : g_vth)
                    + (size_t)(h*HD + r)*L + j0 + g*16 + c*8;
                *(uint4*)(sm + 18432 + plane*9216 + g*2304 + r*48 + c*16) = *(const uint4*)src;
            }
        }
        __syncthreads();

        float s_[8][4];
#pragma unroll
        for (int nt = 0; nt < 8; nt++)
#pragma unroll
            for (int e = 0; e < 4; e++) s_[nt][e] = 0.f;
#pragma unroll
        for (int sl = 0; sl < 3; sl++){
            uint32_t bh[4][4], bl[4][4];
#pragma unroll
            for (int p = 0; p < 4; p++){
                ldB(bh[p], sb +        (uint32_t)(sl*3072), p*16, lane);
                ldB(bl[p], sb + 9216 + (uint32_t)(sl*3072), p*16, lane);
            }
#pragma unroll
            for (int nt = 0; nt < 8; nt++){
                const uint32_t* bhp = &bh[nt>>1][(nt&1)*2];
                const uint32_t* blp = &bl[nt>>1][(nt&1)*2];
                mma16816(s_[nt], qh[sl], bhp);
                mma16816(s_[nt], ql[sl], bhp);
                mma16816(s_[nt], qh[sl], blp);
            }
        }

#pragma unroll
        for (int nt = 0; nt < 8; nt++)
#pragma unroll
            for (int e = 0; e < 2; e++){
                int i = m0 + wid*16 + r0 + e*8;
                float2 b = *(const float2*)(g_bias + (size_t)h*LL + (size_t)i*L
                                            + j0 + nt*8 + c0);
                s_[nt][e*2]   = fmaf(s_[nt][e*2],   sc, b.x);
                s_[nt][e*2+1] = fmaf(s_[nt][e*2+1], sc, b.y);
            }

#pragma unroll
        for (int e = 0; e < 2; e++){
            float mx = -INFINITY;
#pragma unroll
            for (int nt = 0; nt < 8; nt++)
                mx = fmaxf(mx, fmaxf(s_[nt][e*2], s_[nt][e*2+1]));
            mx = fmaxf(mx, __shfl_xor_sync(0xffffffffu, mx, 1));
            mx = fmaxf(mx, __shfl_xor_sync(0xffffffffu, mx, 2));
            float mn = fmaxf(mrow[e], mx);
            float alpha = __expf(mrow[e] - mn);
            mrow[e] = mn;
            float sum = 0.f;
#pragma unroll
            for (int nt = 0; nt < 8; nt++){
                float p0 = __expf(s_[nt][e*2]   - mn);
                float p1 = __expf(s_[nt][e*2+1] - mn);
                s_[nt][e*2] = p0; s_[nt][e*2+1] = p1;
                sum += p0 + p1;
            }
            sum += __shfl_xor_sync(0xffffffffu, sum, 1);
            sum += __shfl_xor_sync(0xffffffffu, sum, 2);
            lrow[e] = lrow[e]*alpha + sum;
#pragma unroll
            for (int dn = 0; dn < 6; dn++){
                o[dn][e*2]   *= alpha;
                o[dn][e*2+1] *= alpha;
            }
        }

#pragma unroll
        for (int g = 0; g < 4; g++){
            uint32_t aH[4], aL[4];
#pragma unroll
            for (int half = 0; half < 2; half++){
                int nt = 2*g + half;
#pragma unroll
                for (int e = 0; e < 2; e++){
                    float p0 = s_[nt][e*2], p1 = s_[nt][e*2+1];
                    uint32_t hi = packbf2(p0, p1);
                    __nv_bfloat162 hv = *(__nv_bfloat162*)&hi;
                    uint32_t lo = packbf2(p0 - __bfloat162float(hv.x),
                                          p1 - __bfloat162float(hv.y));
                    aH[half*2 + e] = hi;
                    aL[half*2 + e] = lo;
                }
            }
            uint32_t vh[3][4], vl[3][4];
#pragma unroll
            for (int q = 0; q < 3; q++){
                ldB(vh[q], sb + 18432 + (uint32_t)(g*2304), q*16, lane);
                ldB(vl[q], sb + 27648 + (uint32_t)(g*2304), q*16, lane);
            }
#pragma unroll
            for (int dn = 0; dn < 6; dn++){
                const uint32_t* vhp = &vh[dn>>1][(dn&1)*2];
                const uint32_t* vlp = &vl[dn>>1][(dn&1)*2];
                mma16816(o[dn], aH, vhp);
                mma16816(o[dn], aL, vhp);
                mma16816(o[dn], aH, vlp);
            }
        }
    }

#pragma unroll
    for (int e = 0; e < 2; e++){
        int i = m0 + wid*16 + r0 + e*8;
        float* op = g_opart + (size_t)js*OPS + (size_t)i*CS + h*HD;
#pragma unroll
        for (int dn = 0; dn < 6; dn++)
            *(float2*)(op + dn*8 + c0) = make_float2(o[dn][e*2], o[dn][e*2+1]);
        if ((lane & 3) == 0)
            g_stat[js*NH*L + h*L + i] = make_float2(mrow[e], lrow[e]);
    }
}

// -------------------- K5: out = single + sigmoid(gate+bg)*(O@Wo^T+bo) -------
__global__ void __launch_bounds__(128) final_kernel(
        const float* __restrict__ Wo, const float* __restrict__ bo,
        const float* __restrict__ single, const float* __restrict__ bg,
        float* __restrict__ out){
    __shared__ float As[32*68];
    __shared__ float Bs[32*68];
    __shared__ float wsm[64][8][NSPLIT];
    const int tid = threadIdx.x;
    const int tx  = tid % 16, ty = tid / 16;
    const int m0 = blockIdx.y*64, n0 = blockIdx.x*64;

    for (int p = tid; p < 64*8; p += 128){
        int row = p >> 3, h = p & 7;
        int gi = m0 + row;
        float2 st[NSPLIT];
        float M = -INFINITY;
#pragma unroll
        for (int s = 0; s < NSPLIT; s++){
            st[s] = g_stat[s*NH*L + h*L + gi];
            M = fmaxf(M, st[s].x);
        }
        float w[NSPLIT], den = 0.f;
#pragma unroll
        for (int s = 0; s < NSPLIT; s++){
            w[s] = __expf(st[s].x - M);
            den = fmaf(w[s], st[s].y, den);
        }
        float inv = 1.f / den;
#pragma unroll
        for (int s = 0; s < NSPLIT; s++) wsm[row][h][s] = w[s]*inv;
    }
    __syncthreads();

    float acc[8][4];
#pragma unroll
    for (int i = 0; i < 8; i++)
#pragma unroll
        for (int j = 0; j < 4; j++) acc[i][j] = 0.f;

    for (int kt = 0; kt < CS; kt += 32){
#pragma unroll
        for (int u = 0; u < 4; u++){
            int t4 = tid + u*128;
            int row = t4 >> 3, kq = t4 & 7;
            int c = kt + kq*4;
            int h = c / HD;
            int gi = m0 + row;
            const float* p = g_opart + (size_t)gi*CS + c;
            float4 v = make_float4(0.f, 0.f, 0.f, 0.f);
#pragma unroll
            for (int s = 0; s < NSPLIT; s++){
                float ws = wsm[row][h][s];
                float4 vs = *(const float4*)(p + (size_t)s*OPS);
                v.x = fmaf(ws, vs.x, v.x); v.y = fmaf(ws, vs.y, v.y);
                v.z = fmaf(ws, vs.z, v.z); v.w = fmaf(ws, vs.w, v.w);
            }
            As[(kq*4+0)*68+row] = v.x; As[(kq*4+1)*68+row] = v.y;
            As[(kq*4+2)*68+row] = v.z; As[(kq*4+3)*68+row] = v.w;
        }
#pragma unroll
        for (int u = 0; u < 4; u++){
            int t4 = tid + u*128;
            int row = t4 >> 3, kq = t4 & 7;
            float4 v = *(const float4*)(Wo + (size_t)(n0 + row)*CS + kt + kq*4);
            Bs[(kq*4+0)*68+row] = v.x; Bs[(kq*4+1)*68+row] = v.y;
            Bs[(kq*4+2)*68+row] = v.z; Bs[(kq*4+3)*68+row] = v.w;
        }
        __syncthreads();
#pragma unroll
        for (int kk = 0; kk < 32; kk++){
            float af[8], bf[4];
            *(float4*)&af[0] = *(const float4*)&As[kk*68 + ty*8];
            *(float4*)&af[4] = *(const float4*)&As[kk*68 + ty*8 + 4];
            *(float4*)&bf[0] = *(const float4*)&Bs[kk*68 + tx*4];
#pragma unroll
            for (int i = 0; i < 8; i++)
#pragma unroll
                for (int j = 0; j < 4; j++)
                    acc[i][j] = fmaf(af[i], bf[j], acc[i][j]);
        }
        __syncthreads();
    }

#pragma unroll
    for (int i = 0; i < 8; i++){
        int row = m0 + ty*8 + i;
#pragma unroll
        for (int j = 0; j < 4; j++){
            int col = n0 + tx*4 + j;
            float y  = acc[i][j] + bo[col];
            float gp = g_gate[(size_t)row*CS + col] + bg[col];
            float gg = 1.f / (1.f + __expf(-gp));
            out[(size_t)row*CS + col] = single[(size_t)row*CS + col] + gg * y;
        }
    }
}

// -------------------- launch --------------------
extern "C" void kernel_launch(void* const* d_in, const int* in_sizes, int n_in,
                              void* d_out, int out_size){
    const float* single = (const float*)d_in[0];
    const float* pair   = (const float*)d_in[1];
    const float* gs     = (const float*)d_in[2];
    const float* bs     = (const float*)d_in[3];
    const float* gz     = (const float*)d_in[4];
    const float* bz     = (const float*)d_in[5];
    const float* Wq     = (const float*)d_in[6];
    const float* Wk     = (const float*)d_in[7];
    const float* Wv     = (const float*)d_in[8];
    const float* Wb     = (const float*)d_in[9];
    const float* Wo     = (const float*)d_in[10];
    const float* bo     = (const float*)d_in[11];
    const float* Wg     = (const float*)d_in[12];
    const float* bg     = (const float*)d_in[13];
    float* out = (float*)d_out;

    // attn_fused now in 4th slot (profiler captures launch #4).
    prep_kernel<<<1152 + L, 128>>>(Wq, Wk, Wv, Wg, single, gs, bs);
    qkvg_mma<<<dim3(1536/64, L/64), 256>>>();
    ln_pair_bias_kernel<<<dim3(6, L), 128>>>((const float4*)pair, gz, bz, Wb);
    attn_fused<<<dim3(NSPLIT, L/64, NH), 128>>>();
    final_kernel<<<dim3(CS/64, L/64), 128>>>(Wo, bo, single, bg, out);
}